// round 1
// baseline (speedup 1.0000x reference)
#include <cuda_runtime.h>
#include <math.h>

// Problem constants
#define NV 96
#define NC 64
#define NH 4
#define NHS 16
#define NL 4
#define NT 64
#define NB 4096
#define NTHREADS 256
#define BTV (NB * NT * NV)

// shared memory layout (in floats)
#define S_XS 0
#define S_HS 4096
#define S_QS 8192
#define S_KS 12288
#define S_VS 16384
#define S_SC 20480
#define S_AS 24576
#define S_RED 28672
#define SMEM_FLOATS 28800
#define SMEM_BYTES (SMEM_FLOATS * 4)

__device__ float g_partial[NB];

// ---------------------------------------------------------------------------
// staging helpers: global -> shared (weights)
// ---------------------------------------------------------------------------
__device__ __forceinline__ void stage_direct(const float* __restrict__ g,
                                             float* __restrict__ s, int n4) {
  for (int i = threadIdx.x; i < n4; i += NTHREADS)
    reinterpret_cast<float4*>(s)[i] = reinterpret_cast<const float4*>(g)[i];
}

// wq/wk/wv layout [H][C][HS] -> smem [c][h*16+s]
__device__ __forceinline__ void stage_qkv(const float* __restrict__ g,
                                          float* __restrict__ s) {
  for (int i = threadIdx.x; i < 4096; i += NTHREADS) {
    int h = i >> 10, c = (i >> 4) & 63, ss = i & 15;
    s[c * 64 + h * 16 + ss] = g[i];
  }
}

// w1 layout [C][4C]; stage column chunk j (64 cols) as smem [c][c2]
__device__ __forceinline__ void stage_w1(const float* __restrict__ g,
                                         float* __restrict__ s, int j) {
  for (int i = threadIdx.x; i < 1024; i += NTHREADS) {
    int c = i >> 4, q = i & 15;
    reinterpret_cast<float4*>(s)[i] =
        reinterpret_cast<const float4*>(g)[c * 64 + j * 16 + q];
  }
}

// ---------------------------------------------------------------------------
// 64x64x64 GEMM: D[t][c2] (=/+=) relu(A[t][:] @ W[:][c2] + bias[c2])
// A, W, D in shared memory. 256 threads: 16 token-groups x 16 col-groups,
// each thread computes a 4x4 tile.
// ---------------------------------------------------------------------------
template <bool RESID, bool RELU>
__device__ __forceinline__ void gemm64(const float* __restrict__ A,
                                       const float* __restrict__ W,
                                       float* __restrict__ D,
                                       const float* __restrict__ bias) {
  const int tid = threadIdx.x;
  const int c2 = (tid & 15) * 4;
  const int t0 = (tid >> 4) * 4;
  float acc[4][4];
#pragma unroll
  for (int i = 0; i < 4; i++)
#pragma unroll
    for (int j = 0; j < 4; j++) acc[i][j] = 0.f;

#pragma unroll
  for (int c = 0; c < 64; c += 4) {
    float wf[16];
#pragma unroll
    for (int r = 0; r < 4; r++) {
      float4 w = *reinterpret_cast<const float4*>(W + (c + r) * 64 + c2);
      wf[r * 4 + 0] = w.x; wf[r * 4 + 1] = w.y;
      wf[r * 4 + 2] = w.z; wf[r * 4 + 3] = w.w;
    }
#pragma unroll
    for (int i = 0; i < 4; i++) {
      float4 a = *reinterpret_cast<const float4*>(A + (t0 + i) * 64 + c);
#pragma unroll
      for (int j = 0; j < 4; j++) {
        acc[i][j] += a.x * wf[0 * 4 + j];
        acc[i][j] += a.y * wf[1 * 4 + j];
        acc[i][j] += a.z * wf[2 * 4 + j];
        acc[i][j] += a.w * wf[3 * 4 + j];
      }
    }
  }

  float bv[4] = {0.f, 0.f, 0.f, 0.f};
  if (bias) {
    float4 b4 = *reinterpret_cast<const float4*>(bias + c2);
    bv[0] = b4.x; bv[1] = b4.y; bv[2] = b4.z; bv[3] = b4.w;
  }
#pragma unroll
  for (int i = 0; i < 4; i++) {
    float v0 = acc[i][0] + bv[0], v1 = acc[i][1] + bv[1];
    float v2 = acc[i][2] + bv[2], v3 = acc[i][3] + bv[3];
    if (RELU) {
      v0 = fmaxf(v0, 0.f); v1 = fmaxf(v1, 0.f);
      v2 = fmaxf(v2, 0.f); v3 = fmaxf(v3, 0.f);
    }
    float* dp = D + (t0 + i) * 64 + c2;
    if (RESID) {
      float4 d = *reinterpret_cast<float4*>(dp);
      d.x += v0; d.y += v1; d.z += v2; d.w += v3;
      *reinterpret_cast<float4*>(dp) = d;
    } else {
      *reinterpret_cast<float4*>(dp) = make_float4(v0, v1, v2, v3);
    }
  }
}

// ---------------------------------------------------------------------------
// LayerNorm over C=64. 4 threads per token (16 elems each), shfl reduce.
// ---------------------------------------------------------------------------
__device__ __forceinline__ void lnorm(const float* __restrict__ X,
                                      float* __restrict__ O,
                                      const float* __restrict__ g,
                                      const float* __restrict__ b) {
  const int tid = threadIdx.x;
  const int t = tid >> 2, p = tid & 3;
  const float* row = X + t * 64 + p * 16;
  float v[16];
#pragma unroll
  for (int r = 0; r < 4; r++) {
    float4 a = *reinterpret_cast<const float4*>(row + r * 4);
    v[r * 4 + 0] = a.x; v[r * 4 + 1] = a.y;
    v[r * 4 + 2] = a.z; v[r * 4 + 3] = a.w;
  }
  float s = 0.f, ss = 0.f;
#pragma unroll
  for (int k = 0; k < 16; k++) { s += v[k]; ss += v[k] * v[k]; }
  s += __shfl_xor_sync(0xffffffffu, s, 1);
  ss += __shfl_xor_sync(0xffffffffu, ss, 1);
  s += __shfl_xor_sync(0xffffffffu, s, 2);
  ss += __shfl_xor_sync(0xffffffffu, ss, 2);
  float mean = s * 0.015625f;
  float var = ss * 0.015625f - mean * mean;
  float inv = rsqrtf(var + 1e-5f);
  const float* gp = g + p * 16;
  const float* bp = b + p * 16;
  float* op = O + t * 64 + p * 16;
#pragma unroll
  for (int r = 0; r < 4; r++) {
    float4 o;
    o.x = (v[r * 4 + 0] - mean) * inv * gp[r * 4 + 0] + bp[r * 4 + 0];
    o.y = (v[r * 4 + 1] - mean) * inv * gp[r * 4 + 1] + bp[r * 4 + 1];
    o.z = (v[r * 4 + 2] - mean) * inv * gp[r * 4 + 2] + bp[r * 4 + 2];
    o.w = (v[r * 4 + 3] - mean) * inv * gp[r * 4 + 3] + bp[r * 4 + 3];
    *reinterpret_cast<float4*>(op + r * 4) = o;
  }
}

// ---------------------------------------------------------------------------
// One attention head: scores + causal softmax + PV. probs in pw (stride 68).
// Output written into hs[t][h*16 + s] (head-concat layout).
// ---------------------------------------------------------------------------
__device__ __forceinline__ void attn_head(const float* __restrict__ qs,
                                          const float* __restrict__ ks,
                                          const float* __restrict__ vs,
                                          float* __restrict__ pw,
                                          float* __restrict__ hs, int h) {
  const int tid = threadIdx.x;
  const int t = tid >> 2, p = tid & 3;
  const float* qrow = qs + t * 64 + h * 16;
  float qv[16];
#pragma unroll
  for (int r = 0; r < 4; r++) {
    float4 a = *reinterpret_cast<const float4*>(qrow + r * 4);
    qv[r * 4 + 0] = a.x; qv[r * 4 + 1] = a.y;
    qv[r * 4 + 2] = a.z; qv[r * 4 + 3] = a.w;
  }
  float e[16];
  float m = -1e30f;
#pragma unroll
  for (int uu = 0; uu < 16; uu++) {
    int u = p * 16 + uu;
    const float* krow = ks + u * 64 + h * 16;
    float d = 0.f;
#pragma unroll
    for (int r = 0; r < 4; r++) {
      float4 k4 = *reinterpret_cast<const float4*>(krow + r * 4);
      d += qv[r * 4 + 0] * k4.x + qv[r * 4 + 1] * k4.y;
      d += qv[r * 4 + 2] * k4.z + qv[r * 4 + 3] * k4.w;
    }
    d = (u <= t) ? d * 0.25f : -1e30f;  // scale = HS^-0.5 = 0.25
    e[uu] = d;
    m = fmaxf(m, d);
  }
  m = fmaxf(m, __shfl_xor_sync(0xffffffffu, m, 1));
  m = fmaxf(m, __shfl_xor_sync(0xffffffffu, m, 2));
  float sum = 0.f;
#pragma unroll
  for (int uu = 0; uu < 16; uu++) {
    float ex = __expf(e[uu] - m);
    e[uu] = ex;
    sum += ex;
  }
  sum += __shfl_xor_sync(0xffffffffu, sum, 1);
  sum += __shfl_xor_sync(0xffffffffu, sum, 2);
  float rinv = 1.f / sum;
  float* prow = pw + t * 68 + p * 16;
#pragma unroll
  for (int uu = 0; uu < 16; uu++) prow[uu] = e[uu] * rinv;
  __syncthreads();

  // o[t][s0..s0+3] = sum_u p[t][u] * v[u][s0..]
  const int s0 = p * 4;
  float4 oa = make_float4(0.f, 0.f, 0.f, 0.f);
  const float* pr = pw + t * 68;
#pragma unroll 8
  for (int u = 0; u < 64; u++) {
    float pv = pr[u];
    float4 vv = *reinterpret_cast<const float4*>(vs + u * 64 + h * 16 + s0);
    oa.x += pv * vv.x; oa.y += pv * vv.y;
    oa.z += pv * vv.z; oa.w += pv * vv.w;
  }
  *reinterpret_cast<float4*>(hs + t * 64 + h * 16 + s0) = oa;
}

// ---------------------------------------------------------------------------
// Main fused kernel: 1 block = 1 sequence.
// ---------------------------------------------------------------------------
__global__ void __launch_bounds__(NTHREADS)
slm_kernel(const int* __restrict__ idx, const int* __restrict__ targets,
           const float* __restrict__ tok_emb, const float* __restrict__ pos_emb,
           const float* __restrict__ ln1_g, const float* __restrict__ ln1_b,
           const float* __restrict__ wq, const float* __restrict__ wk,
           const float* __restrict__ wv, const float* __restrict__ wo,
           const float* __restrict__ bo, const float* __restrict__ ln2_g,
           const float* __restrict__ ln2_b, const float* __restrict__ w1,
           const float* __restrict__ b1, const float* __restrict__ w2,
           const float* __restrict__ b2, const float* __restrict__ lnf_g,
           const float* __restrict__ lnf_b, const float* __restrict__ lm_w,
           const float* __restrict__ lm_b, float* __restrict__ out,
           int write_logits) {
  extern __shared__ float sm[];
  float* xs = sm + S_XS;
  float* hs = sm + S_HS;
  float* qs = sm + S_QS;
  float* ks = sm + S_KS;
  float* vs = sm + S_VS;
  float* sc = sm + S_SC;   // weight staging / probs / logits scratch
  float* as_ = sm + S_AS;  // MLP activations
  float* sred = sm + S_RED;

  const int b = blockIdx.x;
  const int tid = threadIdx.x;

  // embedding: x = tok_emb[idx] + pos_emb
  const int* ib = idx + b * NT;
  for (int i = tid; i < NT * NC; i += NTHREADS) {
    int t = i >> 6, c = i & 63;
    xs[i] = tok_emb[ib[t] * NC + c] + pos_emb[i];
  }
  __syncthreads();

  for (int l = 0; l < NL; l++) {
    // ---- attention block ----
    lnorm(xs, hs, ln1_g + l * NC, ln1_b + l * NC);
    __syncthreads();

    stage_qkv(wq + l * 4096, sc); __syncthreads();
    gemm64<false, false>(hs, sc, qs, nullptr); __syncthreads();
    stage_qkv(wk + l * 4096, sc); __syncthreads();
    gemm64<false, false>(hs, sc, ks, nullptr); __syncthreads();
    stage_qkv(wv + l * 4096, sc); __syncthreads();
    gemm64<false, false>(hs, sc, vs, nullptr); __syncthreads();

    for (int h = 0; h < NH; h++) {
      attn_head(qs, ks, vs, sc, hs, h);  // internal sync between softmax & PV
      __syncthreads();
    }

    stage_direct(wo + l * 4096, sc, 1024); __syncthreads();
    gemm64<true, false>(hs, sc, xs, bo + l * NC); __syncthreads();

    // ---- MLP block ----
    lnorm(xs, hs, ln2_g + l * NC, ln2_b + l * NC);
    __syncthreads();
    for (int j = 0; j < 4; j++) {
      stage_w1(w1 + l * 16384, sc, j); __syncthreads();
      gemm64<false, true>(hs, sc, as_, b1 + l * 256 + j * 64); __syncthreads();
      stage_direct(w2 + l * 16384 + j * 4096, sc, 1024); __syncthreads();
      gemm64<true, false>(as_, sc, xs, (j == 3) ? (b2 + l * NC) : nullptr);
      __syncthreads();
    }
  }

  // ---- final LN + LM head + loss ----
  lnorm(xs, hs, lnf_g, lnf_b);
  stage_direct(lm_w, qs, 1536);  // lm_w [64][96] into qs region
  __syncthreads();

  float* sl = sc;  // logits scratch [64][96]
  if (tid < 192) {
    int cg = tid % 24;  // col group (4 cols)
    int tg = tid / 24;  // token group (8 tokens)
    int vv0 = cg * 4;
    float acc[8][4];
#pragma unroll
    for (int i = 0; i < 8; i++)
#pragma unroll
      for (int j = 0; j < 4; j++) acc[i][j] = 0.f;
    for (int c = 0; c < 64; c++) {
      float4 w = *reinterpret_cast<const float4*>(qs + c * 96 + vv0);
#pragma unroll
      for (int i = 0; i < 8; i++) {
        float a = hs[(tg * 8 + i) * 64 + c];
        acc[i][0] += a * w.x; acc[i][1] += a * w.y;
        acc[i][2] += a * w.z; acc[i][3] += a * w.w;
      }
    }
    float4 b4 = *reinterpret_cast<const float4*>(lm_b + vv0);
#pragma unroll
    for (int i = 0; i < 8; i++) {
      int t = tg * 8 + i;
      float4 o = make_float4(acc[i][0] + b4.x, acc[i][1] + b4.y,
                             acc[i][2] + b4.z, acc[i][3] + b4.w);
      *reinterpret_cast<float4*>(sl + t * 96 + vv0) = o;
      if (write_logits)
        *reinterpret_cast<float4*>(out + (size_t)(b * NT + t) * NV + vv0) = o;
    }
  }
  __syncthreads();

  // per-row log-softmax at target; 4 threads/row
  {
    int t = tid >> 2, p = tid & 3;
    const float* row = sl + t * 96 + p * 24;
    float m = -1e30f;
#pragma unroll
    for (int j = 0; j < 24; j++) m = fmaxf(m, row[j]);
    m = fmaxf(m, __shfl_xor_sync(0xffffffffu, m, 1));
    m = fmaxf(m, __shfl_xor_sync(0xffffffffu, m, 2));
    float se = 0.f;
#pragma unroll
    for (int j = 0; j < 24; j++) se += __expf(row[j] - m);
    se += __shfl_xor_sync(0xffffffffu, se, 1);
    se += __shfl_xor_sync(0xffffffffu, se, 2);
    float lse = m + logf(se);
    int tgt = targets[b * NT + t];
    float contrib = 0.f;
    int rel = tgt - p * 24;
    if (rel >= 0 && rel < 24) contrib = row[rel] - lse;
    contrib += __shfl_xor_sync(0xffffffffu, contrib, 1);
    contrib += __shfl_xor_sync(0xffffffffu, contrib, 2);
    if (p == 0) sred[t] = contrib;
  }
  __syncthreads();
  if (tid < 64) {
    float v = sred[tid];
#pragma unroll
    for (int o = 16; o; o >>= 1) v += __shfl_xor_sync(0xffffffffu, v, o);
    if ((tid & 31) == 0) sred[64 + (tid >> 5)] = v;
  }
  __syncthreads();
  if (tid == 0) g_partial[b] = sred[64] + sred[65];
}

// deterministic reduction of per-sequence loss partials
__global__ void loss_reduce_kernel(float* __restrict__ dst) {
  __shared__ float sh[8];
  float v = 0.f;
  for (int i = threadIdx.x; i < NB; i += NTHREADS) v += g_partial[i];
#pragma unroll
  for (int o = 16; o; o >>= 1) v += __shfl_xor_sync(0xffffffffu, v, o);
  if ((threadIdx.x & 31) == 0) sh[threadIdx.x >> 5] = v;
  __syncthreads();
  if (threadIdx.x == 0) {
    float s = 0.f;
    for (int w = 0; w < 8; w++) s += sh[w];
    dst[0] = -s / (float)(NB * NT);
  }
}

extern "C" void kernel_launch(void* const* d_in, const int* in_sizes, int n_in,
                              void* d_out, int out_size) {
  const int* idx = (const int*)d_in[0];
  const int* targets = (const int*)d_in[1];
  const float* tok_emb = (const float*)d_in[2];
  const float* pos_emb = (const float*)d_in[3];
  const float* ln1_g = (const float*)d_in[4];
  const float* ln1_b = (const float*)d_in[5];
  const float* wq = (const float*)d_in[6];
  const float* wk = (const float*)d_in[7];
  const float* wv = (const float*)d_in[8];
  const float* wo = (const float*)d_in[9];
  const float* bo = (const float*)d_in[10];
  const float* ln2_g = (const float*)d_in[11];
  const float* ln2_b = (const float*)d_in[12];
  const float* w1 = (const float*)d_in[13];
  const float* b1 = (const float*)d_in[14];
  const float* w2 = (const float*)d_in[15];
  const float* b2 = (const float*)d_in[16];
  const float* lnf_g = (const float*)d_in[17];
  const float* lnf_b = (const float*)d_in[18];
  const float* lm_w = (const float*)d_in[19];
  const float* lm_b = (const float*)d_in[20];
  float* out = (float*)d_out;

  cudaFuncSetAttribute(slm_kernel, cudaFuncAttributeMaxDynamicSharedMemorySize,
                       SMEM_BYTES);

  int write_logits = (out_size >= BTV) ? 1 : 0;
  slm_kernel<<<NB, NTHREADS, SMEM_BYTES>>>(
      idx, targets, tok_emb, pos_emb, ln1_g, ln1_b, wq, wk, wv, wo, bo, ln2_g,
      ln2_b, w1, b1, w2, b2, lnf_g, lnf_b, lm_w, lm_b, out, write_logits);

  if (out_size > BTV) {
    loss_reduce_kernel<<<1, NTHREADS>>>(out + BTV);
  } else if (out_size < BTV) {
    // output is loss-only
    loss_reduce_kernel<<<1, NTHREADS>>>(out);
  }
}

// round 2
// speedup vs baseline: 1.0022x; 1.0022x over previous
#include <cuda_runtime.h>
#include <math.h>

// Problem constants
#define NV 96
#define NC 64
#define NH 4
#define NHS 16
#define NL 4
#define NT 64
#define NB 4096
#define NTHREADS 256
#define BTV (NB * NT * NV)

// shared memory layout (in floats)
#define S_XS 0
#define S_HS 4096
#define S_QS 8192
#define S_KS 12288
#define S_VS 16384
#define S_SC 20480
#define S_AS 24576
#define S_RED 28672
#define SMEM_FLOATS 28800
#define SMEM_BYTES (SMEM_FLOATS * 4)

__device__ float g_partial[NB];

// ---------------------------------------------------------------------------
// staging helpers: global -> shared (weights)
// ---------------------------------------------------------------------------
__device__ __forceinline__ void stage_direct(const float* __restrict__ g,
                                             float* __restrict__ s, int n4) {
  for (int i = threadIdx.x; i < n4; i += NTHREADS)
    reinterpret_cast<float4*>(s)[i] = reinterpret_cast<const float4*>(g)[i];
}

// wq/wk/wv layout [H][C][HS] -> smem [c][h*16+s]
__device__ __forceinline__ void stage_qkv(const float* __restrict__ g,
                                          float* __restrict__ s) {
  for (int i = threadIdx.x; i < 4096; i += NTHREADS) {
    int h = i >> 10, c = (i >> 4) & 63, ss = i & 15;
    s[c * 64 + h * 16 + ss] = g[i];
  }
}

// w1 layout [C][4C]; stage column chunk j (64 cols) as smem [c][c2]
__device__ __forceinline__ void stage_w1(const float* __restrict__ g,
                                         float* __restrict__ s, int j) {
  for (int i = threadIdx.x; i < 1024; i += NTHREADS) {
    int c = i >> 4, q = i & 15;
    reinterpret_cast<float4*>(s)[i] =
        reinterpret_cast<const float4*>(g)[c * 64 + j * 16 + q];
  }
}

// ---------------------------------------------------------------------------
// 64x64x64 GEMM: D[t][c2] (=/+=) relu(A[t][:] @ W[:][c2] + bias[c2])
// A, W, D in shared memory. 256 threads: 16 token-groups x 16 col-groups,
// each thread computes a 4x4 tile.
// ---------------------------------------------------------------------------
template <bool RESID, bool RELU>
__device__ __forceinline__ void gemm64(const float* __restrict__ A,
                                       const float* __restrict__ W,
                                       float* __restrict__ D,
                                       const float* __restrict__ bias) {
  const int tid = threadIdx.x;
  const int c2 = (tid & 15) * 4;
  const int t0 = (tid >> 4) * 4;
  float acc[4][4];
#pragma unroll
  for (int i = 0; i < 4; i++)
#pragma unroll
    for (int j = 0; j < 4; j++) acc[i][j] = 0.f;

#pragma unroll
  for (int c = 0; c < 64; c += 4) {
    float wf[16];
#pragma unroll
    for (int r = 0; r < 4; r++) {
      float4 w = *reinterpret_cast<const float4*>(W + (c + r) * 64 + c2);
      wf[r * 4 + 0] = w.x; wf[r * 4 + 1] = w.y;
      wf[r * 4 + 2] = w.z; wf[r * 4 + 3] = w.w;
    }
#pragma unroll
    for (int i = 0; i < 4; i++) {
      float4 a = *reinterpret_cast<const float4*>(A + (t0 + i) * 64 + c);
#pragma unroll
      for (int j = 0; j < 4; j++) {
        acc[i][j] += a.x * wf[0 * 4 + j];
        acc[i][j] += a.y * wf[1 * 4 + j];
        acc[i][j] += a.z * wf[2 * 4 + j];
        acc[i][j] += a.w * wf[3 * 4 + j];
      }
    }
  }

  float bv[4] = {0.f, 0.f, 0.f, 0.f};
  if (bias) {
    float4 b4 = *reinterpret_cast<const float4*>(bias + c2);
    bv[0] = b4.x; bv[1] = b4.y; bv[2] = b4.z; bv[3] = b4.w;
  }
#pragma unroll
  for (int i = 0; i < 4; i++) {
    float v0 = acc[i][0] + bv[0], v1 = acc[i][1] + bv[1];
    float v2 = acc[i][2] + bv[2], v3 = acc[i][3] + bv[3];
    if (RELU) {
      v0 = fmaxf(v0, 0.f); v1 = fmaxf(v1, 0.f);
      v2 = fmaxf(v2, 0.f); v3 = fmaxf(v3, 0.f);
    }
    float* dp = D + (t0 + i) * 64 + c2;
    if (RESID) {
      float4 d = *reinterpret_cast<float4*>(dp);
      d.x += v0; d.y += v1; d.z += v2; d.w += v3;
      *reinterpret_cast<float4*>(dp) = d;
    } else {
      *reinterpret_cast<float4*>(dp) = make_float4(v0, v1, v2, v3);
    }
  }
}

// ---------------------------------------------------------------------------
// LayerNorm over C=64. 4 threads per token (16 elems each), shfl reduce.
// ---------------------------------------------------------------------------
__device__ __forceinline__ void lnorm(const float* __restrict__ X,
                                      float* __restrict__ O,
                                      const float* __restrict__ g,
                                      const float* __restrict__ b) {
  const int tid = threadIdx.x;
  const int t = tid >> 2, p = tid & 3;
  const float* row = X + t * 64 + p * 16;
  float v[16];
#pragma unroll
  for (int r = 0; r < 4; r++) {
    float4 a = *reinterpret_cast<const float4*>(row + r * 4);
    v[r * 4 + 0] = a.x; v[r * 4 + 1] = a.y;
    v[r * 4 + 2] = a.z; v[r * 4 + 3] = a.w;
  }
  float s = 0.f, ss = 0.f;
#pragma unroll
  for (int k = 0; k < 16; k++) { s += v[k]; ss += v[k] * v[k]; }
  s += __shfl_xor_sync(0xffffffffu, s, 1);
  ss += __shfl_xor_sync(0xffffffffu, ss, 1);
  s += __shfl_xor_sync(0xffffffffu, s, 2);
  ss += __shfl_xor_sync(0xffffffffu, ss, 2);
  float mean = s * 0.015625f;
  float var = ss * 0.015625f - mean * mean;
  float inv = rsqrtf(var + 1e-5f);
  const float* gp = g + p * 16;
  const float* bp = b + p * 16;
  float* op = O + t * 64 + p * 16;
#pragma unroll
  for (int r = 0; r < 4; r++) {
    float4 o;
    o.x = (v[r * 4 + 0] - mean) * inv * gp[r * 4 + 0] + bp[r * 4 + 0];
    o.y = (v[r * 4 + 1] - mean) * inv * gp[r * 4 + 1] + bp[r * 4 + 1];
    o.z = (v[r * 4 + 2] - mean) * inv * gp[r * 4 + 2] + bp[r * 4 + 2];
    o.w = (v[r * 4 + 3] - mean) * inv * gp[r * 4 + 3] + bp[r * 4 + 3];
    *reinterpret_cast<float4*>(op + r * 4) = o;
  }
}

// ---------------------------------------------------------------------------
// One attention head: scores + causal softmax + PV. probs in pw (stride 68).
// Output written into hs[t][h*16 + s] (head-concat layout).
// ---------------------------------------------------------------------------
__device__ __forceinline__ void attn_head(const float* __restrict__ qs,
                                          const float* __restrict__ ks,
                                          const float* __restrict__ vs,
                                          float* __restrict__ pw,
                                          float* __restrict__ hs, int h) {
  const int tid = threadIdx.x;
  const int t = tid >> 2, p = tid & 3;
  const float* qrow = qs + t * 64 + h * 16;
  float qv[16];
#pragma unroll
  for (int r = 0; r < 4; r++) {
    float4 a = *reinterpret_cast<const float4*>(qrow + r * 4);
    qv[r * 4 + 0] = a.x; qv[r * 4 + 1] = a.y;
    qv[r * 4 + 2] = a.z; qv[r * 4 + 3] = a.w;
  }
  float e[16];
  float m = -1e30f;
#pragma unroll
  for (int uu = 0; uu < 16; uu++) {
    int u = p * 16 + uu;
    const float* krow = ks + u * 64 + h * 16;
    float d = 0.f;
#pragma unroll
    for (int r = 0; r < 4; r++) {
      float4 k4 = *reinterpret_cast<const float4*>(krow + r * 4);
      d += qv[r * 4 + 0] * k4.x + qv[r * 4 + 1] * k4.y;
      d += qv[r * 4 + 2] * k4.z + qv[r * 4 + 3] * k4.w;
    }
    d = (u <= t) ? d * 0.25f : -1e30f;  // scale = HS^-0.5 = 0.25
    e[uu] = d;
    m = fmaxf(m, d);
  }
  m = fmaxf(m, __shfl_xor_sync(0xffffffffu, m, 1));
  m = fmaxf(m, __shfl_xor_sync(0xffffffffu, m, 2));
  float sum = 0.f;
#pragma unroll
  for (int uu = 0; uu < 16; uu++) {
    float ex = __expf(e[uu] - m);
    e[uu] = ex;
    sum += ex;
  }
  sum += __shfl_xor_sync(0xffffffffu, sum, 1);
  sum += __shfl_xor_sync(0xffffffffu, sum, 2);
  float rinv = 1.f / sum;
  float* prow = pw + t * 68 + p * 16;
#pragma unroll
  for (int uu = 0; uu < 16; uu++) prow[uu] = e[uu] * rinv;
  __syncthreads();

  // o[t][s0..s0+3] = sum_u p[t][u] * v[u][s0..]
  const int s0 = p * 4;
  float4 oa = make_float4(0.f, 0.f, 0.f, 0.f);
  const float* pr = pw + t * 68;
#pragma unroll 8
  for (int u = 0; u < 64; u++) {
    float pv = pr[u];
    float4 vv = *reinterpret_cast<const float4*>(vs + u * 64 + h * 16 + s0);
    oa.x += pv * vv.x; oa.y += pv * vv.y;
    oa.z += pv * vv.z; oa.w += pv * vv.w;
  }
  *reinterpret_cast<float4*>(hs + t * 64 + h * 16 + s0) = oa;
}

// ---------------------------------------------------------------------------
// Main fused kernel: 1 block = 1 sequence.
// ---------------------------------------------------------------------------
__global__ void __launch_bounds__(NTHREADS)
slm_kernel(const int* __restrict__ idx, const int* __restrict__ targets,
           const float* __restrict__ tok_emb, const float* __restrict__ pos_emb,
           const float* __restrict__ ln1_g, const float* __restrict__ ln1_b,
           const float* __restrict__ wq, const float* __restrict__ wk,
           const float* __restrict__ wv, const float* __restrict__ wo,
           const float* __restrict__ bo, const float* __restrict__ ln2_g,
           const float* __restrict__ ln2_b, const float* __restrict__ w1,
           const float* __restrict__ b1, const float* __restrict__ w2,
           const float* __restrict__ b2, const float* __restrict__ lnf_g,
           const float* __restrict__ lnf_b, const float* __restrict__ lm_w,
           const float* __restrict__ lm_b, float* __restrict__ out,
           int write_logits) {
  extern __shared__ float sm[];
  float* xs = sm + S_XS;
  float* hs = sm + S_HS;
  float* qs = sm + S_QS;
  float* ks = sm + S_KS;
  float* vs = sm + S_VS;
  float* sc = sm + S_SC;   // weight staging / probs / logits scratch
  float* as_ = sm + S_AS;  // MLP activations
  float* sred = sm + S_RED;

  const int b = blockIdx.x;
  const int tid = threadIdx.x;

  // embedding: x = tok_emb[idx] + pos_emb
  const int* ib = idx + b * NT;
  for (int i = tid; i < NT * NC; i += NTHREADS) {
    int t = i >> 6, c = i & 63;
    xs[i] = tok_emb[ib[t] * NC + c] + pos_emb[i];
  }
  __syncthreads();

  for (int l = 0; l < NL; l++) {
    // ---- attention block ----
    lnorm(xs, hs, ln1_g + l * NC, ln1_b + l * NC);
    __syncthreads();

    stage_qkv(wq + l * 4096, sc); __syncthreads();
    gemm64<false, false>(hs, sc, qs, nullptr); __syncthreads();
    stage_qkv(wk + l * 4096, sc); __syncthreads();
    gemm64<false, false>(hs, sc, ks, nullptr); __syncthreads();
    stage_qkv(wv + l * 4096, sc); __syncthreads();
    gemm64<false, false>(hs, sc, vs, nullptr); __syncthreads();

    for (int h = 0; h < NH; h++) {
      attn_head(qs, ks, vs, sc, hs, h);  // internal sync between softmax & PV
      __syncthreads();
    }

    stage_direct(wo + l * 4096, sc, 1024); __syncthreads();
    gemm64<true, false>(hs, sc, xs, bo + l * NC); __syncthreads();

    // ---- MLP block ----
    lnorm(xs, hs, ln2_g + l * NC, ln2_b + l * NC);
    __syncthreads();
    for (int j = 0; j < 4; j++) {
      stage_w1(w1 + l * 16384, sc, j); __syncthreads();
      gemm64<false, true>(hs, sc, as_, b1 + l * 256 + j * 64); __syncthreads();
      stage_direct(w2 + l * 16384 + j * 4096, sc, 1024); __syncthreads();
      gemm64<true, false>(as_, sc, xs, (j == 3) ? (b2 + l * NC) : nullptr);
      __syncthreads();
    }
  }

  // ---- final LN + LM head + loss ----
  lnorm(xs, hs, lnf_g, lnf_b);
  stage_direct(lm_w, qs, 1536);  // lm_w [64][96] into qs region
  __syncthreads();

  float* sl = sc;  // logits scratch [64][96]
  if (tid < 192) {
    int cg = tid % 24;  // col group (4 cols)
    int tg = tid / 24;  // token group (8 tokens)
    int vv0 = cg * 4;
    float acc[8][4];
#pragma unroll
    for (int i = 0; i < 8; i++)
#pragma unroll
      for (int j = 0; j < 4; j++) acc[i][j] = 0.f;
    for (int c = 0; c < 64; c++) {
      float4 w = *reinterpret_cast<const float4*>(qs + c * 96 + vv0);
#pragma unroll
      for (int i = 0; i < 8; i++) {
        float a = hs[(tg * 8 + i) * 64 + c];
        acc[i][0] += a * w.x; acc[i][1] += a * w.y;
        acc[i][2] += a * w.z; acc[i][3] += a * w.w;
      }
    }
    float4 b4 = *reinterpret_cast<const float4*>(lm_b + vv0);
#pragma unroll
    for (int i = 0; i < 8; i++) {
      int t = tg * 8 + i;
      float4 o = make_float4(acc[i][0] + b4.x, acc[i][1] + b4.y,
                             acc[i][2] + b4.z, acc[i][3] + b4.w);
      *reinterpret_cast<float4*>(sl + t * 96 + vv0) = o;
      if (write_logits)
        *reinterpret_cast<float4*>(out + (size_t)(b * NT + t) * NV + vv0) = o;
    }
  }
  __syncthreads();

  // per-row log-softmax at target; 4 threads/row
  {
    int t = tid >> 2, p = tid & 3;
    const float* row = sl + t * 96 + p * 24;
    float m = -1e30f;
#pragma unroll
    for (int j = 0; j < 24; j++) m = fmaxf(m, row[j]);
    m = fmaxf(m, __shfl_xor_sync(0xffffffffu, m, 1));
    m = fmaxf(m, __shfl_xor_sync(0xffffffffu, m, 2));
    float se = 0.f;
#pragma unroll
    for (int j = 0; j < 24; j++) se += __expf(row[j] - m);
    se += __shfl_xor_sync(0xffffffffu, se, 1);
    se += __shfl_xor_sync(0xffffffffu, se, 2);
    float lse = m + logf(se);
    int tgt = targets[b * NT + t];
    float contrib = 0.f;
    int rel = tgt - p * 24;
    if (rel >= 0 && rel < 24) contrib = row[rel] - lse;
    contrib += __shfl_xor_sync(0xffffffffu, contrib, 1);
    contrib += __shfl_xor_sync(0xffffffffu, contrib, 2);
    if (p == 0) sred[t] = contrib;
  }
  __syncthreads();
  if (tid < 64) {
    float v = sred[tid];
#pragma unroll
    for (int o = 16; o; o >>= 1) v += __shfl_xor_sync(0xffffffffu, v, o);
    if ((tid & 31) == 0) sred[64 + (tid >> 5)] = v;
  }
  __syncthreads();
  if (tid == 0) g_partial[b] = sred[64] + sred[65];
}

// deterministic reduction of per-sequence loss partials
__global__ void loss_reduce_kernel(float* __restrict__ dst) {
  __shared__ float sh[8];
  float v = 0.f;
  for (int i = threadIdx.x; i < NB; i += NTHREADS) v += g_partial[i];
#pragma unroll
  for (int o = 16; o; o >>= 1) v += __shfl_xor_sync(0xffffffffu, v, o);
  if ((threadIdx.x & 31) == 0) sh[threadIdx.x >> 5] = v;
  __syncthreads();
  if (threadIdx.x == 0) {
    float s = 0.f;
    for (int w = 0; w < 8; w++) s += sh[w];
    dst[0] = -s / (float)(NB * NT);
  }
}

extern "C" void kernel_launch(void* const* d_in, const int* in_sizes, int n_in,
                              void* d_out, int out_size) {
  const int* idx = (const int*)d_in[0];
  const int* targets = (const int*)d_in[1];
  const float* tok_emb = (const float*)d_in[2];
  const float* pos_emb = (const float*)d_in[3];
  const float* ln1_g = (const float*)d_in[4];
  const float* ln1_b = (const float*)d_in[5];
  const float* wq = (const float*)d_in[6];
  const float* wk = (const float*)d_in[7];
  const float* wv = (const float*)d_in[8];
  const float* wo = (const float*)d_in[9];
  const float* bo = (const float*)d_in[10];
  const float* ln2_g = (const float*)d_in[11];
  const float* ln2_b = (const float*)d_in[12];
  const float* w1 = (const float*)d_in[13];
  const float* b1 = (const float*)d_in[14];
  const float* w2 = (const float*)d_in[15];
  const float* b2 = (const float*)d_in[16];
  const float* lnf_g = (const float*)d_in[17];
  const float* lnf_b = (const float*)d_in[18];
  const float* lm_w = (const float*)d_in[19];
  const float* lm_b = (const float*)d_in[20];
  float* out = (float*)d_out;

  cudaFuncSetAttribute(slm_kernel, cudaFuncAttributeMaxDynamicSharedMemorySize,
                       SMEM_BYTES);

  int write_logits = (out_size >= BTV) ? 1 : 0;
  slm_kernel<<<NB, NTHREADS, SMEM_BYTES>>>(
      idx, targets, tok_emb, pos_emb, ln1_g, ln1_b, wq, wk, wv, wo, bo, ln2_g,
      ln2_b, w1, b1, w2, b2, lnf_g, lnf_b, lm_w, lm_b, out, write_logits);

  if (out_size > BTV) {
    loss_reduce_kernel<<<1, NTHREADS>>>(out + BTV);
  } else if (out_size < BTV) {
    // output is loss-only
    loss_reduce_kernel<<<1, NTHREADS>>>(out);
  }
}

// round 5
// speedup vs baseline: 1.9705x; 1.9662x over previous
#include <cuda_runtime.h>
#include <cuda_fp16.h>
#include <mma.h>
#include <stdint.h>
#include <math.h>

using namespace nvcuda;

#define NTHREADS 256
#define NCTAS 2048
#define BTV (4096 * 64 * 96)

// smem byte offsets
#define O_XS 0        // xs fp32 [128][68]           34816
#define O_AA 34816    // A operand fp16 [128][72]    18432
#define O_AM 53248    // A operand (MLP mid) fp16    18432
#define O_D 71680     // D scratch fp32 [128][68]    34816
#define O_B 106496    // B operand fp16 [64][72]      9216
#define O_Q 115712    // q fp16 [128][72]            18432
#define O_K 134144
#define O_V 152576
#define O_RED 171008  // 136 floats
#define SMEM_BYTES 171552
// overlays at end: hs fp32 @ O_D ; lm_w fp32 @ O_XS ; logits [128][96] @ O_Q

__device__ __align__(16) __half g_wqkv[49152];  // [(l*3+m)][n=h*16+s][k]
__device__ __align__(16) __half g_wo[16384];    // [l][n][k]
__device__ __align__(16) __half g_w1[65536];    // [(l*4+j)][n][k]
__device__ __align__(16) __half g_w2[65536];    // [(l*4+j)][n][k]
__device__ float g_partial[NCTAS];

// ---------------- building blocks ---------------------------------------
// stage 64x64 fp16 [n][k] (k contiguous) into smem [n][72]
__device__ __forceinline__ void stageB(const __half* __restrict__ g,
                                       __half* s, int tid) {
  const uint4* src = (const uint4*)g;
  for (int i = tid; i < 512; i += NTHREADS) {
    int n = i >> 3, c = i & 7;
    *(uint4*)(s + n * 72 + c * 8) = src[i];
  }
}

// WMMA 128x64x64: D(fp32,[128] stride 68) = A(fp16,[128] stride 72) @ B^T
// B smem [n][k] stride 72 -> col_major fragment. 8 warps, warp w = rows w*16.
__device__ __forceinline__ void wgemm(const __half* A, const __half* B,
                                      float* D, int tid) {
  const int w = tid >> 5;
  wmma::fragment<wmma::accumulator, 16, 16, 16, float> acc[4];
#pragma unroll
  for (int n = 0; n < 4; n++) wmma::fill_fragment(acc[n], 0.f);
#pragma unroll
  for (int k = 0; k < 4; k++) {
    wmma::fragment<wmma::matrix_a, 16, 16, 16, half, wmma::row_major> fa;
    wmma::load_matrix_sync(fa, A + w * 16 * 72 + k * 16, 72);
#pragma unroll
    for (int n = 0; n < 4; n++) {
      wmma::fragment<wmma::matrix_b, 16, 16, 16, half, wmma::col_major> fb;
      wmma::load_matrix_sync(fb, B + n * 16 * 72 + k * 16, 72);
      wmma::mma_sync(acc[n], fa, fb, acc[n]);
    }
  }
#pragma unroll
  for (int n = 0; n < 4; n++)
    wmma::store_matrix_sync(D + w * 16 * 68 + n * 16, acc[n], 68,
                            wmma::mem_row_major);
}

// LayerNorm of xs row -> v[64]
__device__ __forceinline__ void ln_row(const float* row, float* v,
                                       const float* __restrict__ g,
                                       const float* __restrict__ b) {
  float s = 0.f, ss = 0.f;
#pragma unroll
  for (int i = 0; i < 16; i++) {
    float4 a = *(const float4*)(row + i * 4);
    v[i * 4] = a.x; v[i * 4 + 1] = a.y; v[i * 4 + 2] = a.z; v[i * 4 + 3] = a.w;
    s += a.x + a.y + a.z + a.w;
    ss += a.x * a.x + a.y * a.y + a.z * a.z + a.w * a.w;
  }
  float mean = s * 0.015625f;
  float inv = rsqrtf(ss * 0.015625f - mean * mean + 1e-5f);
#pragma unroll
  for (int c = 0; c < 64; c++)
    v[c] = (v[c] - mean) * inv * __ldg(g + c) + __ldg(b + c);
}

// fp32 v[64] -> fp16 row at stride 144B
__device__ __forceinline__ void row_to_h16(const float* v, char* dst) {
#pragma unroll
  for (int q8 = 0; q8 < 8; q8++) {
    __half2 h[4];
#pragma unroll
    for (int e = 0; e < 4; e++)
      h[e] = __floats2half2_rn(v[q8 * 8 + e * 2], v[q8 * 8 + e * 2 + 1]);
    *(uint4*)(dst + q8 * 16) = *(uint4*)h;
  }
}

// ---------------- prep: transpose+convert weights to fp16 ---------------
__global__ void prep_kernel(const float* __restrict__ wq,
                            const float* __restrict__ wk,
                            const float* __restrict__ wv,
                            const float* __restrict__ wo,
                            const float* __restrict__ w1,
                            const float* __restrict__ w2) {
  int i = blockIdx.x * blockDim.x + threadIdx.x;
  if (i < 49152) {  // wqkv
    int l = i / 12288, rr = i % 12288;
    int m = rr / 4096, r2 = rr % 4096;
    int n = r2 >> 6, k = r2 & 63;
    int h = n >> 4, s = n & 15;
    const float* src = (m == 0) ? wq : (m == 1) ? wk : wv;
    g_wqkv[i] = __float2half(src[l * 4096 + h * 1024 + k * 16 + s]);
  } else if (i < 65536) {  // wo: [l][n][k] = wo[l][k][n]
    int j = i - 49152;
    int l = j >> 12, n = (j >> 6) & 63, k = j & 63;
    g_wo[j] = __float2half(wo[l * 4096 + k * 64 + n]);
  } else if (i < 131072) {  // w1: [(l*4+jj)][n][k] = w1[l][k][jj*64+n]
    int j = i - 65536;
    int lj = j >> 12, n = (j >> 6) & 63, k = j & 63;
    int l = lj >> 2, jj = lj & 3;
    g_w1[j] = __float2half(w1[l * 16384 + k * 256 + jj * 64 + n]);
  } else if (i < 196608) {  // w2: [(l*4+jj)][n][k] = w2[l][jj*64+k][n]
    int j = i - 131072;
    int lj = j >> 12, n = (j >> 6) & 63, k = j & 63;
    int l = lj >> 2, jj = lj & 3;
    g_w2[j] = __float2half(w2[l * 16384 + (jj * 64 + k) * 64 + n]);
  }
}

// ---------------- main fused kernel: 1 CTA = 2 sequences (M=128) --------
__global__ void __launch_bounds__(NTHREADS) slm_kernel(
    const int* __restrict__ idx, const int* __restrict__ targets,
    const float* __restrict__ tok_emb, const float* __restrict__ pos_emb,
    const float* __restrict__ ln1_g, const float* __restrict__ ln1_b,
    const float* __restrict__ bo, const float* __restrict__ ln2_g,
    const float* __restrict__ ln2_b, const float* __restrict__ b1,
    const float* __restrict__ b2, const float* __restrict__ lnf_g,
    const float* __restrict__ lnf_b, const float* __restrict__ lm_w,
    const float* __restrict__ lm_b, float* __restrict__ out,
    int write_logits) {
  extern __shared__ char sm[];
  float* xs = (float*)(sm + O_XS);
  __half* aA = (__half*)(sm + O_AA);
  __half* aM = (__half*)(sm + O_AM);
  float* Ds = (float*)(sm + O_D);
  __half* Bs = (__half*)(sm + O_B);
  float* sred = (float*)(sm + O_RED);
  const int b = blockIdx.x;
  const int tid = threadIdx.x;

  // embedding
  for (int i = tid; i < 8192; i += NTHREADS) {
    int r = i >> 6, c = i & 63;
    xs[r * 68 + c] =
        tok_emb[idx[b * 128 + r] * 64 + c] + pos_emb[(r & 63) * 64 + c];
  }
  __syncthreads();

  for (int l = 0; l < 4; l++) {
    // ---- ln1 -> A operand ----
    if (tid < 128) {
      float v[64];
      ln_row(xs + tid * 68, v, ln1_g + l * 64, ln1_b + l * 64);
      row_to_h16(v, (char*)(aA + tid * 72));
    }
    // ---- Q,K,V GEMMs ----
    for (int m = 0; m < 3; m++) {
      stageB(g_wqkv + (l * 3 + m) * 4096, Bs, tid);
      __syncthreads();
      wgemm(aA, Bs, Ds, tid);
      __syncthreads();
      if (tid < 128) {
        float r[64];
        const float* dr = Ds + tid * 68;
#pragma unroll
        for (int c = 0; c < 64; c++) r[c] = dr[c];
        char* dst = sm + (m == 0 ? O_Q : m == 1 ? O_K : O_V) + tid * 144;
        row_to_h16(r, dst);
      }
      __syncthreads();
    }
    // ---- attention: 2 threads per row, fp32 math on fp16 q/k/v ----
    {
      const int r = tid >> 1, p = tid & 1;
      const int s0 = (r >> 6) << 6, t = r & 63;
      const char* qh = sm + O_Q;
      const char* kh = sm + O_K;
      const char* vh = sm + O_V;
      for (int h = 0; h < 4; h++) {
        float qv[16];
        {
          uint4 u0 = *(const uint4*)(qh + r * 144 + h * 32);
          uint4 u1 = *(const uint4*)(qh + r * 144 + h * 32 + 16);
          const __half2* hp0 = (const __half2*)&u0;
          const __half2* hp1 = (const __half2*)&u1;
#pragma unroll
          for (int e = 0; e < 4; e++) {
            float2 f = __half22float2(hp0[e]);
            qv[e * 2] = f.x; qv[e * 2 + 1] = f.y;
            f = __half22float2(hp1[e]);
            qv[8 + e * 2] = f.x; qv[8 + e * 2 + 1] = f.y;
          }
        }
        float e[32];
        float mx = -1e30f;
#pragma unroll 4
        for (int uu = 0; uu < 32; uu++) {
          int ul = p * 32 + uu;
          const char* krow = kh + (s0 + ul) * 144 + h * 32;
          uint4 u0 = *(const uint4*)(krow);
          uint4 u1 = *(const uint4*)(krow + 16);
          const __half2* k0 = (const __half2*)&u0;
          const __half2* k1 = (const __half2*)&u1;
          float d = 0.f;
#pragma unroll
          for (int q2 = 0; q2 < 4; q2++) {
            float2 f = __half22float2(k0[q2]);
            d += qv[q2 * 2] * f.x + qv[q2 * 2 + 1] * f.y;
            f = __half22float2(k1[q2]);
            d += qv[8 + q2 * 2] * f.x + qv[8 + q2 * 2 + 1] * f.y;
          }
          d = (ul <= t) ? d * 0.25f : -1e30f;
          e[uu] = d;
          mx = fmaxf(mx, d);
        }
        mx = fmaxf(mx, __shfl_xor_sync(0xffffffffu, mx, 1));
        float sum = 0.f;
#pragma unroll
        for (int uu = 0; uu < 32; uu++) {
          e[uu] = __expf(e[uu] - mx);
          sum += e[uu];
        }
        sum += __shfl_xor_sync(0xffffffffu, sum, 1);
        float rinv = 1.f / sum;
        float o[16];
#pragma unroll
        for (int s = 0; s < 16; s++) o[s] = 0.f;
#pragma unroll 4
        for (int uu = 0; uu < 32; uu++) {
          float pv = e[uu];
          const char* vrow = vh + (s0 + p * 32 + uu) * 144 + h * 32;
          uint4 u0 = *(const uint4*)(vrow);
          uint4 u1 = *(const uint4*)(vrow + 16);
          const __half2* v0 = (const __half2*)&u0;
          const __half2* v1 = (const __half2*)&u1;
#pragma unroll
          for (int q2 = 0; q2 < 4; q2++) {
            float2 f = __half22float2(v0[q2]);
            o[q2 * 2] += pv * f.x; o[q2 * 2 + 1] += pv * f.y;
            f = __half22float2(v1[q2]);
            o[8 + q2 * 2] += pv * f.x; o[8 + q2 * 2 + 1] += pv * f.y;
          }
        }
#pragma unroll
        for (int s = 0; s < 16; s++)
          o[s] = (o[s] + __shfl_xor_sync(0xffffffffu, o[s], 1)) * rinv;
        if (p == 0) {
          __half2 h2[8];
#pragma unroll
          for (int e2 = 0; e2 < 8; e2++)
            h2[e2] = __floats2half2_rn(o[e2 * 2], o[e2 * 2 + 1]);
          *(uint4*)((char*)(aA + r * 72) + h * 32) = *(uint4*)&h2[0];
          *(uint4*)((char*)(aA + r * 72) + h * 32 + 16) = *(uint4*)&h2[4];
        }
      }
    }
    __syncthreads();
    // ---- WO GEMM + residual ----
    stageB(g_wo + l * 4096, Bs, tid);
    __syncthreads();
    wgemm(aA, Bs, Ds, tid);
    __syncthreads();
    if (tid < 128) {
      float* xr = xs + tid * 68;
      const float* dr = Ds + tid * 68;
      const float* bp = bo + l * 64;
#pragma unroll
      for (int c = 0; c < 64; c++) xr[c] += dr[c] + __ldg(bp + c);
    }
    __syncthreads();
    // ---- ln2 -> A, MLP 4 chunks ----
    if (tid < 128) {
      float v[64];
      ln_row(xs + tid * 68, v, ln2_g + l * 64, ln2_b + l * 64);
      row_to_h16(v, (char*)(aA + tid * 72));
    }
    for (int j = 0; j < 4; j++) {
      stageB(g_w1 + (l * 4 + j) * 4096, Bs, tid);
      __syncthreads();
      wgemm(aA, Bs, Ds, tid);
      __syncthreads();
      if (tid < 128) {
        float r[64];
        const float* dr = Ds + tid * 68;
        const float* bp = b1 + l * 256 + j * 64;
#pragma unroll
        for (int c = 0; c < 64; c++)
          r[c] = fmaxf(dr[c] + __ldg(bp + c), 0.f);
        row_to_h16(r, (char*)(aM + tid * 72));
      }
      __syncthreads();
      stageB(g_w2 + (l * 4 + j) * 4096, Bs, tid);
      __syncthreads();
      wgemm(aM, Bs, Ds, tid);
      __syncthreads();
      if (tid < 128) {
        float* xr = xs + tid * 68;
        const float* dr = Ds + tid * 68;
        const float* bp = (j == 3) ? (b2 + l * 64) : nullptr;
#pragma unroll
        for (int c = 0; c < 64; c++)
          xr[c] += dr[c] + (bp ? __ldg(bp + c) : 0.f);
      }
      __syncthreads();
    }
  }

  // ---- final LN -> hs (overlay at O_D), lm_w -> smem @ O_XS after use ----
  float* hs = (float*)(sm + O_D);
  if (tid < 128) {
    float v[64];
    ln_row(xs + tid * 68, v, lnf_g, lnf_b);
    float* op = hs + tid * 68;
#pragma unroll
    for (int c = 0; c < 64; c++) op[c] = v[c];
  }
  __syncthreads();
  float* lw = (float*)(sm + O_XS);
  for (int i = tid; i < 1536; i += NTHREADS)
    ((float4*)lw)[i] = ((const float4*)lm_w)[i];
  __syncthreads();

  // ---- logits: fp32, 192 threads x 2 passes ----
  float* sl = (float*)(sm + O_Q);
  for (int pass = 0; pass < 2; pass++) {
    int base = pass * 64;
    if (tid < 192) {
      int cg = tid % 24, tg = tid / 24;
      int vv0 = cg * 4;
      float acc[8][4];
#pragma unroll
      for (int i = 0; i < 8; i++)
#pragma unroll
        for (int q = 0; q < 4; q++) acc[i][q] = 0.f;
      for (int c = 0; c < 64; c++) {
        float4 w = *(const float4*)(lw + c * 96 + vv0);
#pragma unroll
        for (int i = 0; i < 8; i++) {
          float a = hs[(base + tg * 8 + i) * 68 + c];
          acc[i][0] += a * w.x; acc[i][1] += a * w.y;
          acc[i][2] += a * w.z; acc[i][3] += a * w.w;
        }
      }
      float4 b4 = *(const float4*)(lm_b + vv0);
#pragma unroll
      for (int i = 0; i < 8; i++) {
        int t = base + tg * 8 + i;
        float4 o = make_float4(acc[i][0] + b4.x, acc[i][1] + b4.y,
                               acc[i][2] + b4.z, acc[i][3] + b4.w);
        *(float4*)(sl + t * 96 + vv0) = o;
        if (write_logits)
          *(float4*)(out + (size_t)(b * 128 + t) * 96 + vv0) = o;
      }
    }
  }
  __syncthreads();

  // ---- loss: 2 threads per row over 96 cols ----
  {
    int r = tid >> 1, p = tid & 1;
    const float* row = sl + r * 96 + p * 48;
    float m = -1e30f;
#pragma unroll
    for (int j = 0; j < 48; j++) m = fmaxf(m, row[j]);
    m = fmaxf(m, __shfl_xor_sync(0xffffffffu, m, 1));
    float se = 0.f;
#pragma unroll
    for (int j = 0; j < 48; j++) se += __expf(row[j] - m);
    se += __shfl_xor_sync(0xffffffffu, se, 1);
    float lse = m + logf(se);
    int tgt = targets[b * 128 + r];
    float contrib = 0.f;
    int rel = tgt - p * 48;
    if (rel >= 0 && rel < 48) contrib = row[rel] - lse;
    contrib += __shfl_xor_sync(0xffffffffu, contrib, 1);
    if (p == 0) sred[r] = contrib;
  }
  __syncthreads();
  if (tid < 128) {
    float v = sred[tid];
#pragma unroll
    for (int o = 16; o; o >>= 1) v += __shfl_xor_sync(0xffffffffu, v, o);
    if ((tid & 31) == 0) sred[128 + (tid >> 5)] = v;
  }
  __syncthreads();
  if (tid == 0)
    g_partial[b] = sred[128] + sred[129] + sred[130] + sred[131];
}

__global__ void loss_reduce_kernel(float* __restrict__ dst) {
  __shared__ float sh[8];
  float v = 0.f;
  for (int i = threadIdx.x; i < NCTAS; i += NTHREADS) v += g_partial[i];
#pragma unroll
  for (int o = 16; o; o >>= 1) v += __shfl_xor_sync(0xffffffffu, v, o);
  if ((threadIdx.x & 31) == 0) sh[threadIdx.x >> 5] = v;
  __syncthreads();
  if (threadIdx.x == 0) {
    float s = 0.f;
    for (int w = 0; w < 8; w++) s += sh[w];
    dst[0] = -s / (float)(4096 * 64);
  }
}

extern "C" void kernel_launch(void* const* d_in, const int* in_sizes, int n_in,
                              void* d_out, int out_size) {
  const int* idx = (const int*)d_in[0];
  const int* targets = (const int*)d_in[1];
  const float* tok_emb = (const float*)d_in[2];
  const float* pos_emb = (const float*)d_in[3];
  const float* ln1_g = (const float*)d_in[4];
  const float* ln1_b = (const float*)d_in[5];
  const float* wq = (const float*)d_in[6];
  const float* wk = (const float*)d_in[7];
  const float* wv = (const float*)d_in[8];
  const float* wo = (const float*)d_in[9];
  const float* bo = (const float*)d_in[10];
  const float* ln2_g = (const float*)d_in[11];
  const float* ln2_b = (const float*)d_in[12];
  const float* w1 = (const float*)d_in[13];
  const float* b1 = (const float*)d_in[14];
  const float* w2 = (const float*)d_in[15];
  const float* b2 = (const float*)d_in[16];
  const float* lnf_g = (const float*)d_in[17];
  const float* lnf_b = (const float*)d_in[18];
  const float* lm_w = (const float*)d_in[19];
  const float* lm_b = (const float*)d_in[20];
  float* out = (float*)d_out;

  cudaFuncSetAttribute(slm_kernel, cudaFuncAttributeMaxDynamicSharedMemorySize,
                       SMEM_BYTES);

  prep_kernel<<<768, 256>>>(wq, wk, wv, wo, w1, w2);

  int write_logits = (out_size >= BTV) ? 1 : 0;
  slm_kernel<<<NCTAS, NTHREADS, SMEM_BYTES>>>(
      idx, targets, tok_emb, pos_emb, ln1_g, ln1_b, bo, ln2_g, ln2_b, b1, b2,
      lnf_g, lnf_b, lm_w, lm_b, out, write_logits);

  if (out_size > BTV)
    loss_reduce_kernel<<<1, NTHREADS>>>(out + BTV);
  else if (out_size < BTV)
    loss_reduce_kernel<<<1, NTHREADS>>>(out);
}

// round 6
// speedup vs baseline: 3.2067x; 1.6274x over previous
#include <cuda_runtime.h>
#include <cuda_fp16.h>
#include <stdint.h>
#include <math.h>

#define NTHREADS 256
#define NCTAS 2048
#define BTV (4096 * 64 * 96)

// smem byte offsets (total 112 KB -> 2 CTAs/SM)
#define O_XS 0        // xs fp32 [128][68]                  34816
#define O_AA 34816    // A operand fp16 [128][64] swizzled  16384
#define O_B 51200     // B operand fp16 [64][64] swizzled    8192
#define O_Q 59392     // q fp16 [128][72] (stride 144B)     18432
#define O_K 77824
#define O_V 96256
#define O_SRED 108544 // 136 floats (tail phase)
#define SMEM_BYTES 114688
// overlays: aM fp16 swizzled @ O_Q ; lm_w fp32 @ O_AA(+O_B) ; logits @ O_Q

// swizzled byte offset for 128B-row fp16 tiles
#define SW(r, inner) ((r) * 128 + ((inner) ^ (((r) & 7) << 4)))

__device__ __align__(16) __half g_wqkv[49152];  // [(l*3+m)][n=h*16+s][k]
__device__ __align__(16) __half g_wo[16384];    // [l][n][k]
__device__ __align__(16) __half g_w1[65536];    // [(l*4+j)][n][k]
__device__ __align__(16) __half g_w2[65536];    // [(l*4+j)][n][k]
__device__ float g_partial[NCTAS];

__device__ __forceinline__ uint32_t smem_u32(const void* p) {
  uint32_t a;
  asm("{ .reg .u64 t; cvta.to.shared.u64 t, %1; cvt.u32.u64 %0, t; }"
      : "=r"(a) : "l"(p));
  return a;
}

// stage 64x64 fp16 [n][k] weight tile into swizzled smem
__device__ __forceinline__ void stageB(const __half* __restrict__ g, char* s,
                                       int tid) {
  const uint4* src = (const uint4*)g;
  for (int i = tid; i < 512; i += NTHREADS) {
    int n = i >> 3, u = (i & 7) * 16;
    *(uint4*)(s + SW(n, u)) = src[i];
  }
}

// core 128x64x64 mma: A swizzled fp16 @ a_addr, B swizzled fp16 @ b_addr
// warp w owns rows w*16..w*16+15; acc[nt][e]: rows w*16+g(+8), col nt*8+tg*2(+1)
__device__ __forceinline__ void gemm_core(uint32_t a_addr, uint32_t b_addr,
                                          int w, int lane, float acc[8][4]) {
#pragma unroll
  for (int nt = 0; nt < 8; nt++)
#pragma unroll
    for (int e = 0; e < 4; e++) acc[nt][e] = 0.f;
  const int l15 = lane & 15;
  const int ahi = (lane >> 4) << 4;  // 0 or 16
  const int rowA = w * 16 + l15;
  const uint32_t a_base = a_addr + rowA * 128;
  const int aswz = (rowA & 7) << 4;
  const int bl = lane & 7;
  const int bhi = (lane & 8) << 1;  // 0 or 16
#pragma unroll
  for (int kt = 0; kt < 4; kt++) {
    uint32_t aa = a_base + ((kt * 32 + ahi) ^ aswz);
    uint32_t a0, a1, a2, a3;
    asm volatile(
        "ldmatrix.sync.aligned.m8n8.x4.shared.b16 {%0,%1,%2,%3}, [%4];"
        : "=r"(a0), "=r"(a1), "=r"(a2), "=r"(a3) : "r"(aa));
#pragma unroll
    for (int nt = 0; nt < 8; nt++) {
      int rowB = nt * 8 + bl;
      uint32_t ba = b_addr + SW(rowB, kt * 32 + bhi);
      uint32_t b0, b1;
      asm volatile("ldmatrix.sync.aligned.m8n8.x2.shared.b16 {%0,%1}, [%2];"
                   : "=r"(b0), "=r"(b1) : "r"(ba));
      asm volatile(
          "mma.sync.aligned.m16n8k16.row.col.f32.f16.f16.f32 "
          "{%0,%1,%2,%3}, {%4,%5,%6,%7}, {%8,%9}, {%0,%1,%2,%3};"
          : "+f"(acc[nt][0]), "+f"(acc[nt][1]), "+f"(acc[nt][2]),
            "+f"(acc[nt][3])
          : "r"(a0), "r"(a1), "r"(a2), "r"(a3), "r"(b0), "r"(b1));
    }
  }
}

// LayerNorm of xs row -> v[64]
__device__ __forceinline__ void ln_row(const float* row, float* v,
                                       const float* __restrict__ g,
                                       const float* __restrict__ b) {
  float s = 0.f, ss = 0.f;
#pragma unroll
  for (int i = 0; i < 16; i++) {
    float4 a = *(const float4*)(row + i * 4);
    v[i * 4] = a.x; v[i * 4 + 1] = a.y; v[i * 4 + 2] = a.z; v[i * 4 + 3] = a.w;
    s += a.x + a.y + a.z + a.w;
    ss += a.x * a.x + a.y * a.y + a.z * a.z + a.w * a.w;
  }
  float mean = s * 0.015625f;
  float inv = rsqrtf(ss * 0.015625f - mean * mean + 1e-5f);
#pragma unroll
  for (int c = 0; c < 64; c++)
    v[c] = (v[c] - mean) * inv * __ldg(g + c) + __ldg(b + c);
}

// fp32 v[64] -> swizzled fp16 A-operand row
__device__ __forceinline__ void row_to_A(const float* v, char* aAc, int r) {
#pragma unroll
  for (int q8 = 0; q8 < 8; q8++) {
    __half2 h[4];
#pragma unroll
    for (int e = 0; e < 4; e++)
      h[e] = __floats2half2_rn(v[q8 * 8 + e * 2], v[q8 * 8 + e * 2 + 1]);
    *(uint4*)(aAc + SW(r, q8 * 16)) = *(uint4*)h;
  }
}

// ---------------- prep: transpose+convert weights to fp16 ---------------
__global__ void prep_kernel(const float* __restrict__ wq,
                            const float* __restrict__ wk,
                            const float* __restrict__ wv,
                            const float* __restrict__ wo,
                            const float* __restrict__ w1,
                            const float* __restrict__ w2) {
  int i = blockIdx.x * blockDim.x + threadIdx.x;
  if (i < 49152) {
    int l = i / 12288, rr = i % 12288;
    int m = rr / 4096, r2 = rr % 4096;
    int n = r2 >> 6, k = r2 & 63;
    int h = n >> 4, s = n & 15;
    const float* src = (m == 0) ? wq : (m == 1) ? wk : wv;
    g_wqkv[i] = __float2half(src[l * 4096 + h * 1024 + k * 16 + s]);
  } else if (i < 65536) {
    int j = i - 49152;
    int l = j >> 12, n = (j >> 6) & 63, k = j & 63;
    g_wo[j] = __float2half(wo[l * 4096 + k * 64 + n]);
  } else if (i < 131072) {
    int j = i - 65536;
    int lj = j >> 12, n = (j >> 6) & 63, k = j & 63;
    int l = lj >> 2, jj = lj & 3;
    g_w1[j] = __float2half(w1[l * 16384 + k * 256 + jj * 64 + n]);
  } else if (i < 196608) {
    int j = i - 131072;
    int lj = j >> 12, n = (j >> 6) & 63, k = j & 63;
    int l = lj >> 2, jj = lj & 3;
    g_w2[j] = __float2half(w2[l * 16384 + (jj * 64 + k) * 64 + n]);
  }
}

// ---------------- main fused kernel: 1 CTA = 2 sequences (M=128) --------
__global__ void __launch_bounds__(NTHREADS, 2) slm_kernel(
    const int* __restrict__ idx, const int* __restrict__ targets,
    const float* __restrict__ tok_emb, const float* __restrict__ pos_emb,
    const float* __restrict__ ln1_g, const float* __restrict__ ln1_b,
    const float* __restrict__ bo, const float* __restrict__ ln2_g,
    const float* __restrict__ ln2_b, const float* __restrict__ b1,
    const float* __restrict__ b2, const float* __restrict__ lnf_g,
    const float* __restrict__ lnf_b, const float* __restrict__ lm_w,
    const float* __restrict__ lm_b, float* __restrict__ out,
    int write_logits) {
  extern __shared__ char sm[];
  float* xs = (float*)(sm + O_XS);
  char* aAc = sm + O_AA;
  char* Bsc = sm + O_B;
  float* sred = (float*)(sm + O_SRED);
  const int b = blockIdx.x;
  const int tid = threadIdx.x;
  const int w = tid >> 5, lane = tid & 31;
  const int g = lane >> 2, tg = lane & 3;
  const int r0 = w * 16 + g;
  const uint32_t smb = smem_u32(sm);
  const uint32_t a_aA = smb + O_AA, a_B = smb + O_B, a_aM = smb + O_Q;

  // embedding
  for (int i = tid; i < 8192; i += NTHREADS) {
    int r = i >> 6, c = i & 63;
    xs[r * 68 + c] =
        tok_emb[idx[b * 128 + r] * 64 + c] + pos_emb[(r & 63) * 64 + c];
  }
  __syncthreads();

  float acc[8][4];

  for (int l = 0; l < 4; l++) {
    // ---- ln1 -> A operand ----
    if (tid < 128) {
      float v[64];
      ln_row(xs + tid * 68, v, ln1_g + l * 64, ln1_b + l * 64);
      row_to_A(v, aAc, tid);
    }
    // ---- Q,K,V GEMMs with in-register fp16 epilogue ----
    for (int m = 0; m < 3; m++) {
      stageB(g_wqkv + (l * 3 + m) * 4096, Bsc, tid);
      __syncthreads();
      gemm_core(a_aA, a_B, w, lane, acc);
      __half* dst = (__half*)(sm + (m == 0 ? O_Q : m == 1 ? O_K : O_V));
#pragma unroll
      for (int nt = 0; nt < 8; nt++) {
        int col = nt * 8 + tg * 2;
        *(__half2*)(dst + r0 * 72 + col) =
            __floats2half2_rn(acc[nt][0], acc[nt][1]);
        *(__half2*)(dst + (r0 + 8) * 72 + col) =
            __floats2half2_rn(acc[nt][2], acc[nt][3]);
      }
      __syncthreads();
    }
    // ---- attention: 2 threads per row ----
    {
      const int r = tid >> 1, p = tid & 1;
      const int s0 = (r >> 6) << 6, t = r & 63;
      const char* qh = sm + O_Q;
      const char* kh = sm + O_K;
      const char* vh = sm + O_V;
      for (int h = 0; h < 4; h++) {
        float qv[16];
        {
          uint4 u0 = *(const uint4*)(qh + r * 144 + h * 32);
          uint4 u1 = *(const uint4*)(qh + r * 144 + h * 32 + 16);
          const __half2* hp0 = (const __half2*)&u0;
          const __half2* hp1 = (const __half2*)&u1;
#pragma unroll
          for (int e = 0; e < 4; e++) {
            float2 f = __half22float2(hp0[e]);
            qv[e * 2] = f.x; qv[e * 2 + 1] = f.y;
            f = __half22float2(hp1[e]);
            qv[8 + e * 2] = f.x; qv[8 + e * 2 + 1] = f.y;
          }
        }
        float e[32];
        float mx = -1e30f;
#pragma unroll 4
        for (int uu = 0; uu < 32; uu++) {
          int ul = p * 32 + uu;
          const char* krow = kh + (s0 + ul) * 144 + h * 32;
          uint4 u0 = *(const uint4*)(krow);
          uint4 u1 = *(const uint4*)(krow + 16);
          const __half2* k0 = (const __half2*)&u0;
          const __half2* k1 = (const __half2*)&u1;
          float d = 0.f;
#pragma unroll
          for (int q2 = 0; q2 < 4; q2++) {
            float2 f = __half22float2(k0[q2]);
            d += qv[q2 * 2] * f.x + qv[q2 * 2 + 1] * f.y;
            f = __half22float2(k1[q2]);
            d += qv[8 + q2 * 2] * f.x + qv[8 + q2 * 2 + 1] * f.y;
          }
          d = (ul <= t) ? d * 0.25f : -1e30f;
          e[uu] = d;
          mx = fmaxf(mx, d);
        }
        mx = fmaxf(mx, __shfl_xor_sync(0xffffffffu, mx, 1));
        float sum = 0.f;
#pragma unroll
        for (int uu = 0; uu < 32; uu++) {
          e[uu] = __expf(e[uu] - mx);
          sum += e[uu];
        }
        sum += __shfl_xor_sync(0xffffffffu, sum, 1);
        float rinv = 1.f / sum;
        float o[16];
#pragma unroll
        for (int s = 0; s < 16; s++) o[s] = 0.f;
#pragma unroll 4
        for (int uu = 0; uu < 32; uu++) {
          float pv = e[uu];
          const char* vrow = vh + (s0 + p * 32 + uu) * 144 + h * 32;
          uint4 u0 = *(const uint4*)(vrow);
          uint4 u1 = *(const uint4*)(vrow + 16);
          const __half2* v0 = (const __half2*)&u0;
          const __half2* v1 = (const __half2*)&u1;
#pragma unroll
          for (int q2 = 0; q2 < 4; q2++) {
            float2 f = __half22float2(v0[q2]);
            o[q2 * 2] += pv * f.x; o[q2 * 2 + 1] += pv * f.y;
            f = __half22float2(v1[q2]);
            o[8 + q2 * 2] += pv * f.x; o[8 + q2 * 2 + 1] += pv * f.y;
          }
        }
#pragma unroll
        for (int s = 0; s < 16; s++)
          o[s] = (o[s] + __shfl_xor_sync(0xffffffffu, o[s], 1)) * rinv;
        if (p == 0) {
          __half2 h2[8];
#pragma unroll
          for (int e2 = 0; e2 < 8; e2++)
            h2[e2] = __floats2half2_rn(o[e2 * 2], o[e2 * 2 + 1]);
          *(uint4*)(aAc + SW(r, h * 32)) = *(uint4*)&h2[0];
          *(uint4*)(aAc + SW(r, h * 32 + 16)) = *(uint4*)&h2[4];
        }
      }
    }
    __syncthreads();
    // ---- WO GEMM: xs += d + bo ----
    stageB(g_wo + l * 4096, Bsc, tid);
    __syncthreads();
    gemm_core(a_aA, a_B, w, lane, acc);
    {
      const float* bp = bo + l * 64;
#pragma unroll
      for (int nt = 0; nt < 8; nt++) {
        int col = nt * 8 + tg * 2;
        float bv0 = __ldg(bp + col), bv1 = __ldg(bp + col + 1);
        xs[r0 * 68 + col] += acc[nt][0] + bv0;
        xs[r0 * 68 + col + 1] += acc[nt][1] + bv1;
        xs[(r0 + 8) * 68 + col] += acc[nt][2] + bv0;
        xs[(r0 + 8) * 68 + col + 1] += acc[nt][3] + bv1;
      }
    }
    __syncthreads();
    // ---- ln2 -> A ----
    if (tid < 128) {
      float v[64];
      ln_row(xs + tid * 68, v, ln2_g + l * 64, ln2_b + l * 64);
      row_to_A(v, aAc, tid);
    }
    // ---- MLP: 4 chunks of 64 hidden ----
    char* aMc = sm + O_Q;  // overlay (q/k/v dead)
    for (int j = 0; j < 4; j++) {
      stageB(g_w1 + (l * 4 + j) * 4096, Bsc, tid);
      __syncthreads();
      gemm_core(a_aA, a_B, w, lane, acc);
      {
        const float* bp = b1 + l * 256 + j * 64;
#pragma unroll
        for (int nt = 0; nt < 8; nt++) {
          int col = nt * 8 + tg * 2;
          float bv0 = __ldg(bp + col), bv1 = __ldg(bp + col + 1);
          *(__half2*)(aMc + SW(r0, col * 2)) = __floats2half2_rn(
              fmaxf(acc[nt][0] + bv0, 0.f), fmaxf(acc[nt][1] + bv1, 0.f));
          *(__half2*)(aMc + SW(r0 + 8, col * 2)) = __floats2half2_rn(
              fmaxf(acc[nt][2] + bv0, 0.f), fmaxf(acc[nt][3] + bv1, 0.f));
        }
      }
      __syncthreads();
      stageB(g_w2 + (l * 4 + j) * 4096, Bsc, tid);
      __syncthreads();
      gemm_core(a_aM, a_B, w, lane, acc);
      {
        const float* bp = (j == 3) ? (b2 + l * 64) : nullptr;
#pragma unroll
        for (int nt = 0; nt < 8; nt++) {
          int col = nt * 8 + tg * 2;
          float bv0 = bp ? __ldg(bp + col) : 0.f;
          float bv1 = bp ? __ldg(bp + col + 1) : 0.f;
          xs[r0 * 68 + col] += acc[nt][0] + bv0;
          xs[r0 * 68 + col + 1] += acc[nt][1] + bv1;
          xs[(r0 + 8) * 68 + col] += acc[nt][2] + bv0;
          xs[(r0 + 8) * 68 + col + 1] += acc[nt][3] + bv1;
        }
      }
      __syncthreads();
    }
  }

  // ---- final LN in-place on xs ----
  if (tid < 128) {
    float v[64];
    ln_row(xs + tid * 68, v, lnf_g, lnf_b);
    float* op = xs + tid * 68;
#pragma unroll
    for (int c = 0; c < 64; c++) op[c] = v[c];
  }
  __syncthreads();
  // lm_w fp32 into aA+B region (6144 floats = 24576 B exactly)
  float* lw = (float*)(sm + O_AA);
  for (int i = tid; i < 1536; i += NTHREADS)
    ((float4*)lw)[i] = ((const float4*)lm_w)[i];
  __syncthreads();

  // ---- logits: fp32, 192 threads x 2 passes; hs = xs ----
  float* sl = (float*)(sm + O_Q);
  for (int pass = 0; pass < 2; pass++) {
    int base = pass * 64;
    if (tid < 192) {
      int cg = tid % 24, tgrp = tid / 24;
      int vv0 = cg * 4;
      float ac[8][4];
#pragma unroll
      for (int i = 0; i < 8; i++)
#pragma unroll
        for (int q = 0; q < 4; q++) ac[i][q] = 0.f;
      for (int c = 0; c < 64; c++) {
        float4 wv4 = *(const float4*)(lw + c * 96 + vv0);
#pragma unroll
        for (int i = 0; i < 8; i++) {
          float a = xs[(base + tgrp * 8 + i) * 68 + c];
          ac[i][0] += a * wv4.x; ac[i][1] += a * wv4.y;
          ac[i][2] += a * wv4.z; ac[i][3] += a * wv4.w;
        }
      }
      float4 b4 = *(const float4*)(lm_b + vv0);
#pragma unroll
      for (int i = 0; i < 8; i++) {
        int t = base + tgrp * 8 + i;
        float4 o = make_float4(ac[i][0] + b4.x, ac[i][1] + b4.y,
                               ac[i][2] + b4.z, ac[i][3] + b4.w);
        *(float4*)(sl + t * 96 + vv0) = o;
        if (write_logits)
          *(float4*)(out + (size_t)(b * 128 + t) * 96 + vv0) = o;
      }
    }
  }
  __syncthreads();

  // ---- loss: 2 threads per row over 96 cols ----
  {
    int r = tid >> 1, p = tid & 1;
    const float* row = sl + r * 96 + p * 48;
    float m = -1e30f;
#pragma unroll
    for (int j = 0; j < 48; j++) m = fmaxf(m, row[j]);
    m = fmaxf(m, __shfl_xor_sync(0xffffffffu, m, 1));
    float se = 0.f;
#pragma unroll
    for (int j = 0; j < 48; j++) se += __expf(row[j] - m);
    se += __shfl_xor_sync(0xffffffffu, se, 1);
    float lse = m + logf(se);
    int tgt = targets[b * 128 + r];
    float contrib = 0.f;
    int rel = tgt - p * 48;
    if (rel >= 0 && rel < 48) contrib = row[rel] - lse;
    contrib += __shfl_xor_sync(0xffffffffu, contrib, 1);
    if (p == 0) sred[r] = contrib;
  }
  __syncthreads();
  if (tid < 128) {
    float v = sred[tid];
#pragma unroll
    for (int o = 16; o; o >>= 1) v += __shfl_xor_sync(0xffffffffu, v, o);
    if ((tid & 31) == 0) sred[128 + (tid >> 5)] = v;
  }
  __syncthreads();
  if (tid == 0)
    g_partial[b] = sred[128] + sred[129] + sred[130] + sred[131];
}

__global__ void loss_reduce_kernel(float* __restrict__ dst) {
  __shared__ float sh[8];
  float v = 0.f;
  for (int i = threadIdx.x; i < NCTAS; i += NTHREADS) v += g_partial[i];
#pragma unroll
  for (int o = 16; o; o >>= 1) v += __shfl_xor_sync(0xffffffffu, v, o);
  if ((threadIdx.x & 31) == 0) sh[threadIdx.x >> 5] = v;
  __syncthreads();
  if (threadIdx.x == 0) {
    float s = 0.f;
    for (int w = 0; w < 8; w++) s += sh[w];
    dst[0] = -s / (float)(4096 * 64);
  }
}

extern "C" void kernel_launch(void* const* d_in, const int* in_sizes, int n_in,
                              void* d_out, int out_size) {
  const int* idx = (const int*)d_in[0];
  const int* targets = (const int*)d_in[1];
  const float* tok_emb = (const float*)d_in[2];
  const float* pos_emb = (const float*)d_in[3];
  const float* ln1_g = (const float*)d_in[4];
  const float* ln1_b = (const float*)d_in[5];
  const float* wq = (const float*)d_in[6];
  const float* wk = (const float*)d_in[7];
  const float* wv = (const float*)d_in[8];
  const float* wo = (const float*)d_in[9];
  const float* bo = (const float*)d_in[10];
  const float* ln2_g = (const float*)d_in[11];
  const float* ln2_b = (const float*)d_in[12];
  const float* w1 = (const float*)d_in[13];
  const float* b1 = (const float*)d_in[14];
  const float* w2 = (const float*)d_in[15];
  const float* b2 = (const float*)d_in[16];
  const float* lnf_g = (const float*)d_in[17];
  const float* lnf_b = (const float*)d_in[18];
  const float* lm_w = (const float*)d_in[19];
  const float* lm_b = (const float*)d_in[20];
  float* out = (float*)d_out;

  cudaFuncSetAttribute(slm_kernel, cudaFuncAttributeMaxDynamicSharedMemorySize,
                       SMEM_BYTES);

  prep_kernel<<<768, 256>>>(wq, wk, wv, wo, w1, w2);

  int write_logits = (out_size >= BTV) ? 1 : 0;
  slm_kernel<<<NCTAS, NTHREADS, SMEM_BYTES>>>(
      idx, targets, tok_emb, pos_emb, ln1_g, ln1_b, bo, ln2_g, ln2_b, b1, b2,
      lnf_g, lnf_b, lm_w, lm_b, out, write_logits);

  if (out_size > BTV)
    loss_reduce_kernel<<<1, NTHREADS>>>(out + BTV);
  else if (out_size < BTV)
    loss_reduce_kernel<<<1, NTHREADS>>>(out);
}

// round 7
// speedup vs baseline: 5.6573x; 1.7642x over previous
#include <cuda_runtime.h>
#include <cuda_fp16.h>
#include <stdint.h>
#include <math.h>

#define NTHREADS 256
#define NCTAS 2048
#define BTV (4096 * 64 * 96)

// smem byte offsets (total <= 110592 -> 2 CTAs/SM)
#define O_XS 0        // xs fp32 [128][68]                  34816
#define O_AA 34816    // A operand fp16 [128][64] swizzled  16384
#define O_B 51200     // B operand fp16 [64][64] swizzled    8192
#define O_Q 59392     // q fp16 swizzled [128][128B]        16384
#define O_K 75776     // k fp16 swizzled                    16384
#define O_V 92160     // v fp16 swizzled                    16384
#define O_SRED 108544 // 136 floats
#define SMEM_BYTES 110592
// overlays: aM @ O_Q (MLP); w2 stage @ O_K (MLP); lm_w fp32 @ O_AA..O_B end;
// logits fp32 [128][96] @ O_Q (49152 = q+k+v exactly)

#define SW(r, inner) ((r) * 128 + ((inner) ^ (((r) & 7) << 4)))

__device__ __align__(16) __half g_wqkv[49152];  // [(l*3+m)][n=h*16+s][k]
__device__ __align__(16) __half g_wo[16384];    // [l][n][k]
__device__ __align__(16) __half g_w1[65536];    // [(l*4+j)][n][k]
__device__ __align__(16) __half g_w2[65536];    // [(l*4+j)][n][k]
__device__ float g_partial[NCTAS];

__device__ __forceinline__ uint32_t smem_u32(const void* p) {
  uint32_t a;
  asm("{ .reg .u64 t; cvta.to.shared.u64 t, %1; cvt.u32.u64 %0, t; }"
      : "=r"(a) : "l"(p));
  return a;
}
__device__ __forceinline__ uint32_t f2h2(float x, float y) {
  __half2 h = __floats2half2_rn(x, y);
  return *(uint32_t*)&h;
}

// stage 64x64 fp16 [n][k] weight tile into swizzled smem
__device__ __forceinline__ void stageB(const __half* __restrict__ g, char* s,
                                       int tid) {
  const uint4* src = (const uint4*)g;
  for (int i = tid; i < 512; i += NTHREADS) {
    int n = i >> 3, u = (i & 7) * 16;
    *(uint4*)(s + SW(n, u)) = src[i];
  }
}

#define LDSM_X4(a0, a1, a2, a3, addr)                                        \
  asm volatile("ldmatrix.sync.aligned.m8n8.x4.shared.b16 {%0,%1,%2,%3}, [%4];" \
               : "=r"(a0), "=r"(a1), "=r"(a2), "=r"(a3) : "r"(addr))
#define LDSM_X2(b0, b1, addr)                                                \
  asm volatile("ldmatrix.sync.aligned.m8n8.x2.shared.b16 {%0,%1}, [%2];"     \
               : "=r"(b0), "=r"(b1) : "r"(addr))
#define LDSM_X2T(b0, b1, addr)                                               \
  asm volatile("ldmatrix.sync.aligned.m8n8.x2.trans.shared.b16 {%0,%1}, [%2];" \
               : "=r"(b0), "=r"(b1) : "r"(addr))
#define MMA16816(c, a0, a1, a2, a3, b0, b1)                                  \
  asm volatile(                                                              \
      "mma.sync.aligned.m16n8k16.row.col.f32.f16.f16.f32 "                   \
      "{%0,%1,%2,%3}, {%4,%5,%6,%7}, {%8,%9}, {%0,%1,%2,%3};"                \
      : "+f"((c)[0]), "+f"((c)[1]), "+f"((c)[2]), "+f"((c)[3])               \
      : "r"(a0), "r"(a1), "r"(a2), "r"(a3), "r"(b0), "r"(b1))

// core 128x64x64 mma: A swizzled @ a_addr, B swizzled @ b_addr
__device__ __forceinline__ void gemm_core(uint32_t a_addr, uint32_t b_addr,
                                          int w, int lane, float acc[8][4]) {
#pragma unroll
  for (int nt = 0; nt < 8; nt++)
#pragma unroll
    for (int e = 0; e < 4; e++) acc[nt][e] = 0.f;
  const int l15 = lane & 15;
  const int ahi = (lane >> 4) << 4;
  const int rowA = w * 16 + l15;
  const uint32_t a_base = a_addr + rowA * 128;
  const int aswz = (rowA & 7) << 4;
  const int bl = lane & 7;
  const int bhi = (lane & 8) << 1;
#pragma unroll
  for (int kt = 0; kt < 4; kt++) {
    uint32_t aa = a_base + ((kt * 32 + ahi) ^ aswz);
    uint32_t a0, a1, a2, a3;
    LDSM_X4(a0, a1, a2, a3, aa);
#pragma unroll
    for (int nt = 0; nt < 8; nt++) {
      uint32_t ba = b_addr + SW(nt * 8 + bl, kt * 32 + bhi);
      uint32_t b0, b1;
      LDSM_X2(b0, b1, ba);
      MMA16816(acc[nt], a0, a1, a2, a3, b0, b1);
    }
  }
}

// LayerNorm of xs row -> v[64]
__device__ __forceinline__ void ln_row(const float* row, float* v,
                                       const float* __restrict__ g,
                                       const float* __restrict__ b) {
  float s = 0.f, ss = 0.f;
#pragma unroll
  for (int i = 0; i < 16; i++) {
    float4 a = *(const float4*)(row + i * 4);
    v[i * 4] = a.x; v[i * 4 + 1] = a.y; v[i * 4 + 2] = a.z; v[i * 4 + 3] = a.w;
    s += a.x + a.y + a.z + a.w;
    ss += a.x * a.x + a.y * a.y + a.z * a.z + a.w * a.w;
  }
  float mean = s * 0.015625f;
  float inv = rsqrtf(ss * 0.015625f - mean * mean + 1e-5f);
#pragma unroll
  for (int c = 0; c < 64; c++)
    v[c] = (v[c] - mean) * inv * __ldg(g + c) + __ldg(b + c);
}

__device__ __forceinline__ void row_to_A(const float* v, char* aAc, int r) {
#pragma unroll
  for (int q8 = 0; q8 < 8; q8++) {
    uint32_t h[4];
#pragma unroll
    for (int e = 0; e < 4; e++)
      h[e] = f2h2(v[q8 * 8 + e * 2], v[q8 * 8 + e * 2 + 1]);
    *(uint4*)(aAc + SW(r, q8 * 16)) = *(uint4*)h;
  }
}

// ---------------- prep ----------------------------------------------------
__global__ void prep_kernel(const float* __restrict__ wq,
                            const float* __restrict__ wk,
                            const float* __restrict__ wv,
                            const float* __restrict__ wo,
                            const float* __restrict__ w1,
                            const float* __restrict__ w2) {
  int i = blockIdx.x * blockDim.x + threadIdx.x;
  if (i < 49152) {
    int l = i / 12288, rr = i % 12288;
    int m = rr / 4096, r2 = rr % 4096;
    int n = r2 >> 6, k = r2 & 63;
    int h = n >> 4, s = n & 15;
    const float* src = (m == 0) ? wq : (m == 1) ? wk : wv;
    g_wqkv[i] = __float2half(src[l * 4096 + h * 1024 + k * 16 + s]);
  } else if (i < 65536) {
    int j = i - 49152;
    int l = j >> 12, n = (j >> 6) & 63, k = j & 63;
    g_wo[j] = __float2half(wo[l * 4096 + k * 64 + n]);
  } else if (i < 131072) {
    int j = i - 65536;
    int lj = j >> 12, n = (j >> 6) & 63, k = j & 63;
    int l = lj >> 2, jj = lj & 3;
    g_w1[j] = __float2half(w1[l * 16384 + k * 256 + jj * 64 + n]);
  } else if (i < 196608) {
    int j = i - 131072;
    int lj = j >> 12, n = (j >> 6) & 63, k = j & 63;
    int l = lj >> 2, jj = lj & 3;
    g_w2[j] = __float2half(w2[l * 16384 + (jj * 64 + k) * 64 + n]);
  }
}

// ---------------- main fused kernel: 1 CTA = 2 sequences ------------------
__global__ void __launch_bounds__(NTHREADS, 2) slm_kernel(
    const int* __restrict__ idx, const int* __restrict__ targets,
    const float* __restrict__ tok_emb, const float* __restrict__ pos_emb,
    const float* __restrict__ ln1_g, const float* __restrict__ ln1_b,
    const float* __restrict__ bo, const float* __restrict__ ln2_g,
    const float* __restrict__ ln2_b, const float* __restrict__ b1,
    const float* __restrict__ b2, const float* __restrict__ lnf_g,
    const float* __restrict__ lnf_b, const float* __restrict__ lm_w,
    const float* __restrict__ lm_b, float* __restrict__ out,
    int write_logits) {
  extern __shared__ char sm[];
  float* xs = (float*)(sm + O_XS);
  char* aAc = sm + O_AA;
  char* Bsc = sm + O_B;
  float* sred = (float*)(sm + O_SRED);
  const int b = blockIdx.x;
  const int tid = threadIdx.x;
  const int w = tid >> 5, lane = tid & 31;
  const int g = lane >> 2, tg = lane & 3;
  const int r0 = w * 16 + g;
  const uint32_t smb = smem_u32(sm);
  const uint32_t a_aA = smb + O_AA, a_B = smb + O_B;
  const uint32_t a_q = smb + O_Q, a_k = smb + O_K, a_v = smb + O_V;

  for (int i = tid; i < 8192; i += NTHREADS) {
    int r = i >> 6, c = i & 63;
    xs[r * 68 + c] =
        tok_emb[idx[b * 128 + r] * 64 + c] + pos_emb[(r & 63) * 64 + c];
  }
  __syncthreads();

  float acc[8][4];

  for (int l = 0; l < 4; l++) {
    if (tid < 128) {
      float v[64];
      ln_row(xs + tid * 68, v, ln1_g + l * 64, ln1_b + l * 64);
      row_to_A(v, aAc, tid);
    }
    // ---- Q,K,V GEMMs -> swizzled q/k/v tiles ----
    for (int m = 0; m < 3; m++) {
      stageB(g_wqkv + (l * 3 + m) * 4096, Bsc, tid);
      __syncthreads();
      gemm_core(a_aA, a_B, w, lane, acc);
      char* dst = sm + (m == 0 ? O_Q : m == 1 ? O_K : O_V);
#pragma unroll
      for (int nt = 0; nt < 8; nt++) {
        int col = nt * 8 + tg * 2;
        *(uint32_t*)(dst + SW(r0, col * 2)) = f2h2(acc[nt][0], acc[nt][1]);
        *(uint32_t*)(dst + SW(r0 + 8, col * 2)) = f2h2(acc[nt][2], acc[nt][3]);
      }
      __syncthreads();
    }
    // ---- attention on tensor cores; warp w owns rows w*16..+15 ----
    {
      const int bl = lane & 7;
      const int l15 = lane & 15;
      const int ahi = (lane >> 4) << 4;
      const int bhi = (lane & 8) << 1;
      const int seq0 = (w >> 2) * 64;           // token base of this warp's seq
      const int tlo = (w & 3) * 16 + g;          // token idx of row r0 in seq
      const int rowA = w * 16 + l15;
      const uint32_t q_base = a_q + rowA * 128;
      const int aswz = (rowA & 7) << 4;
#pragma unroll
      for (int h = 0; h < 4; h++) {
        float S[8][4];
#pragma unroll
        for (int nt = 0; nt < 8; nt++)
#pragma unroll
          for (int e = 0; e < 4; e++) S[nt][e] = 0.f;
        uint32_t a0, a1, a2, a3;
        LDSM_X4(a0, a1, a2, a3, q_base + ((h * 32 + ahi) ^ aswz));
#pragma unroll
        for (int nt = 0; nt < 8; nt++) {
          uint32_t b0, b1;
          LDSM_X2(b0, b1, a_k + SW(seq0 + nt * 8 + bl, h * 32 + bhi));
          MMA16816(S[nt], a0, a1, a2, a3, b0, b1);
        }
        // mask + scale + softmax (rows tlo and tlo+8)
        float mx0 = -1e30f, mx1 = -1e30f;
#pragma unroll
        for (int nt = 0; nt < 8; nt++) {
          int c0 = nt * 8 + tg * 2;
          S[nt][0] = (c0 <= tlo) ? S[nt][0] * 0.25f : -1e30f;
          S[nt][1] = (c0 + 1 <= tlo) ? S[nt][1] * 0.25f : -1e30f;
          S[nt][2] = (c0 <= tlo + 8) ? S[nt][2] * 0.25f : -1e30f;
          S[nt][3] = (c0 + 1 <= tlo + 8) ? S[nt][3] * 0.25f : -1e30f;
          mx0 = fmaxf(mx0, fmaxf(S[nt][0], S[nt][1]));
          mx1 = fmaxf(mx1, fmaxf(S[nt][2], S[nt][3]));
        }
        mx0 = fmaxf(mx0, __shfl_xor_sync(0xffffffffu, mx0, 1));
        mx0 = fmaxf(mx0, __shfl_xor_sync(0xffffffffu, mx0, 2));
        mx1 = fmaxf(mx1, __shfl_xor_sync(0xffffffffu, mx1, 1));
        mx1 = fmaxf(mx1, __shfl_xor_sync(0xffffffffu, mx1, 2));
        float sum0 = 0.f, sum1 = 0.f;
#pragma unroll
        for (int nt = 0; nt < 8; nt++) {
          S[nt][0] = __expf(S[nt][0] - mx0);
          S[nt][1] = __expf(S[nt][1] - mx0);
          S[nt][2] = __expf(S[nt][2] - mx1);
          S[nt][3] = __expf(S[nt][3] - mx1);
          sum0 += S[nt][0] + S[nt][1];
          sum1 += S[nt][2] + S[nt][3];
        }
        sum0 += __shfl_xor_sync(0xffffffffu, sum0, 1);
        sum0 += __shfl_xor_sync(0xffffffffu, sum0, 2);
        sum1 += __shfl_xor_sync(0xffffffffu, sum1, 1);
        sum1 += __shfl_xor_sync(0xffffffffu, sum1, 2);
        float ri0 = 1.f / sum0, ri1 = 1.f / sum1;
        // P acc -> A fragments (register identity)
        uint32_t Pa[4][4];
#pragma unroll
        for (int kb = 0; kb < 4; kb++) {
          Pa[kb][0] = f2h2(S[2 * kb][0] * ri0, S[2 * kb][1] * ri0);
          Pa[kb][1] = f2h2(S[2 * kb][2] * ri1, S[2 * kb][3] * ri1);
          Pa[kb][2] = f2h2(S[2 * kb + 1][0] * ri0, S[2 * kb + 1][1] * ri0);
          Pa[kb][3] = f2h2(S[2 * kb + 1][2] * ri1, S[2 * kb + 1][3] * ri1);
        }
        // O = P @ V via ldmatrix.trans on the normal v tile
        float O[2][4];
#pragma unroll
        for (int nt = 0; nt < 2; nt++)
#pragma unroll
          for (int e = 0; e < 4; e++) O[nt][e] = 0.f;
#pragma unroll
        for (int kb = 0; kb < 4; kb++) {
          int ur = seq0 + kb * 16 + bl + ((lane & 8) ? 8 : 0);
#pragma unroll
          for (int nt = 0; nt < 2; nt++) {
            uint32_t b0, b1;
            LDSM_X2T(b0, b1, a_v + SW(ur, h * 32 + nt * 16));
            MMA16816(O[nt], Pa[kb][0], Pa[kb][1], Pa[kb][2], Pa[kb][3], b0, b1);
          }
        }
#pragma unroll
        for (int nt = 0; nt < 2; nt++) {
          int col = h * 16 + nt * 8 + tg * 2;
          *(uint32_t*)(aAc + SW(r0, col * 2)) = f2h2(O[nt][0], O[nt][1]);
          *(uint32_t*)(aAc + SW(r0 + 8, col * 2)) = f2h2(O[nt][2], O[nt][3]);
        }
      }
    }
    __syncthreads();
    // ---- WO GEMM: xs += d + bo ----
    stageB(g_wo + l * 4096, Bsc, tid);
    __syncthreads();
    gemm_core(a_aA, a_B, w, lane, acc);
    {
      const float* bp = bo + l * 64;
#pragma unroll
      for (int nt = 0; nt < 8; nt++) {
        int col = nt * 8 + tg * 2;
        float bv0 = __ldg(bp + col), bv1 = __ldg(bp + col + 1);
        xs[r0 * 68 + col] += acc[nt][0] + bv0;
        xs[r0 * 68 + col + 1] += acc[nt][1] + bv1;
        xs[(r0 + 8) * 68 + col] += acc[nt][2] + bv0;
        xs[(r0 + 8) * 68 + col + 1] += acc[nt][3] + bv1;
      }
    }
    __syncthreads();
    if (tid < 128) {
      float v[64];
      ln_row(xs + tid * 68, v, ln2_g + l * 64, ln2_b + l * 64);
      row_to_A(v, aAc, tid);
    }
    // ---- MLP: w1 chunk in O_B, w2 chunk staged into dead O_K ----
    char* aMc = sm + O_Q;
    const uint32_t a_aM = a_q;
    for (int j = 0; j < 4; j++) {
      stageB(g_w1 + (l * 4 + j) * 4096, Bsc, tid);
      stageB(g_w2 + (l * 4 + j) * 4096, sm + O_K, tid);
      __syncthreads();
      gemm_core(a_aA, a_B, w, lane, acc);
      {
        const float* bp = b1 + l * 256 + j * 64;
#pragma unroll
        for (int nt = 0; nt < 8; nt++) {
          int col = nt * 8 + tg * 2;
          float bv0 = __ldg(bp + col), bv1 = __ldg(bp + col + 1);
          *(uint32_t*)(aMc + SW(r0, col * 2)) = f2h2(
              fmaxf(acc[nt][0] + bv0, 0.f), fmaxf(acc[nt][1] + bv1, 0.f));
          *(uint32_t*)(aMc + SW(r0 + 8, col * 2)) = f2h2(
              fmaxf(acc[nt][2] + bv0, 0.f), fmaxf(acc[nt][3] + bv1, 0.f));
        }
      }
      __syncthreads();
      gemm_core(a_aM, a_k, w, lane, acc);
      {
        const float* bp = (j == 3) ? (b2 + l * 64) : nullptr;
#pragma unroll
        for (int nt = 0; nt < 8; nt++) {
          int col = nt * 8 + tg * 2;
          float bv0 = bp ? __ldg(bp + col) : 0.f;
          float bv1 = bp ? __ldg(bp + col + 1) : 0.f;
          xs[r0 * 68 + col] += acc[nt][0] + bv0;
          xs[r0 * 68 + col + 1] += acc[nt][1] + bv1;
          xs[(r0 + 8) * 68 + col] += acc[nt][2] + bv0;
          xs[(r0 + 8) * 68 + col + 1] += acc[nt][3] + bv1;
        }
      }
      __syncthreads();
    }
  }

  // ---- final LN in-place on xs ----
  if (tid < 128) {
    float v[64];
    ln_row(xs + tid * 68, v, lnf_g, lnf_b);
    float* op = xs + tid * 68;
#pragma unroll
    for (int c = 0; c < 64; c++) op[c] = v[c];
  }
  __syncthreads();
  float* lw = (float*)(sm + O_AA);
  for (int i = tid; i < 1536; i += NTHREADS)
    ((float4*)lw)[i] = ((const float4*)lm_w)[i];
  __syncthreads();

  // ---- logits ----
  float* sl = (float*)(sm + O_Q);
  for (int pass = 0; pass < 2; pass++) {
    int base = pass * 64;
    if (tid < 192) {
      int cg = tid % 24, tgrp = tid / 24;
      int vv0 = cg * 4;
      float ac[8][4];
#pragma unroll
      for (int i = 0; i < 8; i++)
#pragma unroll
        for (int q = 0; q < 4; q++) ac[i][q] = 0.f;
      for (int c = 0; c < 64; c++) {
        float4 wv4 = *(const float4*)(lw + c * 96 + vv0);
#pragma unroll
        for (int i = 0; i < 8; i++) {
          float a = xs[(base + tgrp * 8 + i) * 68 + c];
          ac[i][0] += a * wv4.x; ac[i][1] += a * wv4.y;
          ac[i][2] += a * wv4.z; ac[i][3] += a * wv4.w;
        }
      }
      float4 b4 = *(const float4*)(lm_b + vv0);
#pragma unroll
      for (int i = 0; i < 8; i++) {
        int t = base + tgrp * 8 + i;
        float4 o = make_float4(ac[i][0] + b4.x, ac[i][1] + b4.y,
                               ac[i][2] + b4.z, ac[i][3] + b4.w);
        *(float4*)(sl + t * 96 + vv0) = o;
        if (write_logits)
          *(float4*)(out + (size_t)(b * 128 + t) * 96 + vv0) = o;
      }
    }
  }
  __syncthreads();

  // ---- loss ----
  {
    int r = tid >> 1, p = tid & 1;
    const float* row = sl + r * 96 + p * 48;
    float m = -1e30f;
#pragma unroll
    for (int j = 0; j < 48; j++) m = fmaxf(m, row[j]);
    m = fmaxf(m, __shfl_xor_sync(0xffffffffu, m, 1));
    float se = 0.f;
#pragma unroll
    for (int j = 0; j < 48; j++) se += __expf(row[j] - m);
    se += __shfl_xor_sync(0xffffffffu, se, 1);
    float lse = m + logf(se);
    int tgt = targets[b * 128 + r];
    float contrib = 0.f;
    int rel = tgt - p * 48;
    if (rel >= 0 && rel < 48) contrib = row[rel] - lse;
    contrib += __shfl_xor_sync(0xffffffffu, contrib, 1);
    if (p == 0) sred[r] = contrib;
  }
  __syncthreads();
  if (tid < 128) {
    float v = sred[tid];
#pragma unroll
    for (int o = 16; o; o >>= 1) v += __shfl_xor_sync(0xffffffffu, v, o);
    if ((tid & 31) == 0) sred[128 + (tid >> 5)] = v;
  }
  __syncthreads();
  if (tid == 0)
    g_partial[b] = sred[128] + sred[129] + sred[130] + sred[131];
}

__global__ void loss_reduce_kernel(float* __restrict__ dst) {
  __shared__ float sh[8];
  float v = 0.f;
  for (int i = threadIdx.x; i < NCTAS; i += NTHREADS) v += g_partial[i];
#pragma unroll
  for (int o = 16; o; o >>= 1) v += __shfl_xor_sync(0xffffffffu, v, o);
  if ((threadIdx.x & 31) == 0) sh[threadIdx.x >> 5] = v;
  __syncthreads();
  if (threadIdx.x == 0) {
    float s = 0.f;
    for (int w = 0; w < 8; w++) s += sh[w];
    dst[0] = -s / (float)(4096 * 64);
  }
}

extern "C" void kernel_launch(void* const* d_in, const int* in_sizes, int n_in,
                              void* d_out, int out_size) {
  const int* idx = (const int*)d_in[0];
  const int* targets = (const int*)d_in[1];
  const float* tok_emb = (const float*)d_in[2];
  const float* pos_emb = (const float*)d_in[3];
  const float* ln1_g = (const float*)d_in[4];
  const float* ln1_b = (const float*)d_in[5];
  const float* wq = (const float*)d_in[6];
  const float* wk = (const float*)d_in[7];
  const float* wv = (const float*)d_in[8];
  const float* wo = (const float*)d_in[9];
  const float* bo = (const float*)d_in[10];
  const float* ln2_g = (const float*)d_in[11];
  const float* ln2_b = (const float*)d_in[12];
  const float* w1 = (const float*)d_in[13];
  const float* b1 = (const float*)d_in[14];
  const float* w2 = (const float*)d_in[15];
  const float* b2 = (const float*)d_in[16];
  const float* lnf_g = (const float*)d_in[17];
  const float* lnf_b = (const float*)d_in[18];
  const float* lm_w = (const float*)d_in[19];
  const float* lm_b = (const float*)d_in[20];
  float* out = (float*)d_out;

  cudaFuncSetAttribute(slm_kernel, cudaFuncAttributeMaxDynamicSharedMemorySize,
                       SMEM_BYTES);

  prep_kernel<<<768, 256>>>(wq, wk, wv, wo, w1, w2);

  int write_logits = (out_size >= BTV) ? 1 : 0;
  slm_kernel<<<NCTAS, NTHREADS, SMEM_BYTES>>>(
      idx, targets, tok_emb, pos_emb, ln1_g, ln1_b, bo, ln2_g, ln2_b, b1, b2,
      lnf_g, lnf_b, lm_w, lm_b, out, write_logits);

  if (out_size > BTV)
    loss_reduce_kernel<<<1, NTHREADS>>>(out + BTV);
  else if (out_size < BTV)
    loss_reduce_kernel<<<1, NTHREADS>>>(out);
}

// round 8
// speedup vs baseline: 5.8758x; 1.0386x over previous
#include <cuda_runtime.h>
#include <cuda_fp16.h>
#include <stdint.h>
#include <math.h>

#define NTHREADS 256
#define NCTAS 2048
#define BTV (4096 * 64 * 96)

// smem byte offsets (total <= 110592 -> 2 CTAs/SM)
#define O_XS 0        // xs fp32 [128][68]                  34816
#define O_AA 34816    // A operand fp16 [128][64] swizzled  16384
#define O_B 51200     // B operand fp16 [64][64] swizzled    8192
#define O_Q 59392     // q fp16 swizzled [128][128B]        16384
#define O_K 75776     // k fp16 swizzled                    16384
#define O_V 92160     // v fp16 swizzled                    16384
#define O_SRED 108544 // 136 floats
#define SMEM_BYTES 110592
// tail overlays: Ah @ O_AA, Al @ O_Q, Bh @ O_K, Bl @ O_K+12288;
// logits fp32 [128][96] @ O_Q (49152 = Q+K+V exactly, written post-GEMM)

#define SW(r, inner) ((r) * 128 + ((inner) ^ (((r) & 7) << 4)))

__device__ __align__(16) __half g_wqkv[49152];  // [(l*3+m)][n=h*16+s][k]
__device__ __align__(16) __half g_wo[16384];    // [l][n][k]
__device__ __align__(16) __half g_w1[65536];    // [(l*4+j)][n][k]
__device__ __align__(16) __half g_w2[65536];    // [(l*4+j)][n][k]
__device__ __align__(16) __half g_lmh[6144];    // lm_w hi [n=96][k=64]
__device__ __align__(16) __half g_lml[6144];    // lm_w lo
__device__ float g_partial[NCTAS];

__device__ __forceinline__ uint32_t smem_u32(const void* p) {
  uint32_t a;
  asm("{ .reg .u64 t; cvta.to.shared.u64 t, %1; cvt.u32.u64 %0, t; }"
      : "=r"(a) : "l"(p));
  return a;
}
__device__ __forceinline__ uint32_t f2h2(float x, float y) {
  __half2 h = __floats2half2_rn(x, y);
  return *(uint32_t*)&h;
}

// stage 64x64 fp16 [n][k] weight tile into swizzled smem
__device__ __forceinline__ void stageB(const __half* __restrict__ g, char* s,
                                       int tid) {
  const uint4* src = (const uint4*)g;
  for (int i = tid; i < 512; i += NTHREADS) {
    int n = i >> 3, u = (i & 7) * 16;
    *(uint4*)(s + SW(n, u)) = src[i];
  }
}
// stage 96x64 fp16 [n][k] tile (LM head)
__device__ __forceinline__ void stageB96(const __half* __restrict__ g, char* s,
                                         int tid) {
  const uint4* src = (const uint4*)g;
  for (int i = tid; i < 768; i += NTHREADS) {
    int n = i >> 3, u = (i & 7) * 16;
    *(uint4*)(s + SW(n, u)) = src[i];
  }
}

#define LDSM_X4(a0, a1, a2, a3, addr)                                        \
  asm volatile("ldmatrix.sync.aligned.m8n8.x4.shared.b16 {%0,%1,%2,%3}, [%4];" \
               : "=r"(a0), "=r"(a1), "=r"(a2), "=r"(a3) : "r"(addr))
#define LDSM_X2(b0, b1, addr)                                                \
  asm volatile("ldmatrix.sync.aligned.m8n8.x2.shared.b16 {%0,%1}, [%2];"     \
               : "=r"(b0), "=r"(b1) : "r"(addr))
#define LDSM_X2T(b0, b1, addr)                                               \
  asm volatile("ldmatrix.sync.aligned.m8n8.x2.trans.shared.b16 {%0,%1}, [%2];" \
               : "=r"(b0), "=r"(b1) : "r"(addr))
#define MMA16816(c, a0, a1, a2, a3, b0, b1)                                  \
  asm volatile(                                                              \
      "mma.sync.aligned.m16n8k16.row.col.f32.f16.f16.f32 "                   \
      "{%0,%1,%2,%3}, {%4,%5,%6,%7}, {%8,%9}, {%0,%1,%2,%3};"                \
      : "+f"((c)[0]), "+f"((c)[1]), "+f"((c)[2]), "+f"((c)[3])               \
      : "r"(a0), "r"(a1), "r"(a2), "r"(a3), "r"(b0), "r"(b1))

// core 128x64x64 mma: A swizzled @ a_addr, B swizzled @ b_addr
__device__ __forceinline__ void gemm_core(uint32_t a_addr, uint32_t b_addr,
                                          int w, int lane, float acc[8][4]) {
#pragma unroll
  for (int nt = 0; nt < 8; nt++)
#pragma unroll
    for (int e = 0; e < 4; e++) acc[nt][e] = 0.f;
  const int l15 = lane & 15;
  const int ahi = (lane >> 4) << 4;
  const int rowA = w * 16 + l15;
  const uint32_t a_base = a_addr + rowA * 128;
  const int aswz = (rowA & 7) << 4;
  const int bl = lane & 7;
  const int bhi = (lane & 8) << 1;
#pragma unroll
  for (int kt = 0; kt < 4; kt++) {
    uint32_t aa = a_base + ((kt * 32 + ahi) ^ aswz);
    uint32_t a0, a1, a2, a3;
    LDSM_X4(a0, a1, a2, a3, aa);
#pragma unroll
    for (int nt = 0; nt < 8; nt++) {
      uint32_t ba = b_addr + SW(nt * 8 + bl, kt * 32 + bhi);
      uint32_t b0, b1;
      LDSM_X2(b0, b1, ba);
      MMA16816(acc[nt], a0, a1, a2, a3, b0, b1);
    }
  }
}

// one accumulation pass of the 128x96x64 LM-head GEMM
__device__ __forceinline__ void lm_pass(uint32_t a_addr, uint32_t b_addr,
                                        int w, int lane, float acc[12][4]) {
  const int l15 = lane & 15;
  const int ahi = (lane >> 4) << 4;
  const int rowA = w * 16 + l15;
  const uint32_t a_base = a_addr + rowA * 128;
  const int aswz = (rowA & 7) << 4;
  const int bl = lane & 7;
  const int bhi = (lane & 8) << 1;
#pragma unroll
  for (int kt = 0; kt < 4; kt++) {
    uint32_t aa = a_base + ((kt * 32 + ahi) ^ aswz);
    uint32_t a0, a1, a2, a3;
    LDSM_X4(a0, a1, a2, a3, aa);
#pragma unroll
    for (int nt = 0; nt < 12; nt++) {
      uint32_t ba = b_addr + SW(nt * 8 + bl, kt * 32 + bhi);
      uint32_t b0, b1;
      LDSM_X2(b0, b1, ba);
      MMA16816(acc[nt], a0, a1, a2, a3, b0, b1);
    }
  }
}

// LayerNorm of xs row -> v[64]
__device__ __forceinline__ void ln_row(const float* row, float* v,
                                       const float* __restrict__ g,
                                       const float* __restrict__ b) {
  float s = 0.f, ss = 0.f;
#pragma unroll
  for (int i = 0; i < 16; i++) {
    float4 a = *(const float4*)(row + i * 4);
    v[i * 4] = a.x; v[i * 4 + 1] = a.y; v[i * 4 + 2] = a.z; v[i * 4 + 3] = a.w;
    s += a.x + a.y + a.z + a.w;
    ss += a.x * a.x + a.y * a.y + a.z * a.z + a.w * a.w;
  }
  float mean = s * 0.015625f;
  float inv = rsqrtf(ss * 0.015625f - mean * mean + 1e-5f);
#pragma unroll
  for (int c = 0; c < 64; c++)
    v[c] = (v[c] - mean) * inv * __ldg(g + c) + __ldg(b + c);
}

__device__ __forceinline__ void row_to_A(const float* v, char* aAc, int r) {
#pragma unroll
  for (int q8 = 0; q8 < 8; q8++) {
    uint32_t h[4];
#pragma unroll
    for (int e = 0; e < 4; e++)
      h[e] = f2h2(v[q8 * 8 + e * 2], v[q8 * 8 + e * 2 + 1]);
    *(uint4*)(aAc + SW(r, q8 * 16)) = *(uint4*)h;
  }
}

// ---------------- prep ----------------------------------------------------
__global__ void prep_kernel(const float* __restrict__ wq,
                            const float* __restrict__ wk,
                            const float* __restrict__ wv,
                            const float* __restrict__ wo,
                            const float* __restrict__ w1,
                            const float* __restrict__ w2,
                            const float* __restrict__ lm_w) {
  int i = blockIdx.x * blockDim.x + threadIdx.x;
  if (i < 49152) {
    int l = i / 12288, rr = i % 12288;
    int m = rr / 4096, r2 = rr % 4096;
    int n = r2 >> 6, k = r2 & 63;
    int h = n >> 4, s = n & 15;
    const float* src = (m == 0) ? wq : (m == 1) ? wk : wv;
    g_wqkv[i] = __float2half(src[l * 4096 + h * 1024 + k * 16 + s]);
  } else if (i < 65536) {
    int j = i - 49152;
    int l = j >> 12, n = (j >> 6) & 63, k = j & 63;
    g_wo[j] = __float2half(wo[l * 4096 + k * 64 + n]);
  } else if (i < 131072) {
    int j = i - 65536;
    int lj = j >> 12, n = (j >> 6) & 63, k = j & 63;
    int l = lj >> 2, jj = lj & 3;
    g_w1[j] = __float2half(w1[l * 16384 + k * 256 + jj * 64 + n]);
  } else if (i < 196608) {
    int j = i - 131072;
    int lj = j >> 12, n = (j >> 6) & 63, k = j & 63;
    int l = lj >> 2, jj = lj & 3;
    g_w2[j] = __float2half(w2[l * 16384 + (jj * 64 + k) * 64 + n]);
  } else if (i < 202752) {
    int j = i - 196608;
    int n = j >> 6, k = j & 63;
    float v = lm_w[k * 96 + n];
    __half hi = __float2half(v);
    g_lmh[j] = hi;
    g_lml[j] = __float2half(v - __half2float(hi));
  }
}

// ---------------- main fused kernel: 1 CTA = 2 sequences ------------------
__global__ void __launch_bounds__(NTHREADS, 2) slm_kernel(
    const int* __restrict__ idx, const int* __restrict__ targets,
    const float* __restrict__ tok_emb, const float* __restrict__ pos_emb,
    const float* __restrict__ ln1_g, const float* __restrict__ ln1_b,
    const float* __restrict__ bo, const float* __restrict__ ln2_g,
    const float* __restrict__ ln2_b, const float* __restrict__ b1,
    const float* __restrict__ b2, const float* __restrict__ lnf_g,
    const float* __restrict__ lnf_b, const float* __restrict__ lm_b,
    float* __restrict__ out, int write_logits) {
  extern __shared__ char sm[];
  float* xs = (float*)(sm + O_XS);
  char* aAc = sm + O_AA;
  char* Bsc = sm + O_B;
  float* sred = (float*)(sm + O_SRED);
  const int b = blockIdx.x;
  const int tid = threadIdx.x;
  const int w = tid >> 5, lane = tid & 31;
  const int g = lane >> 2, tg = lane & 3;
  const int r0 = w * 16 + g;
  const uint32_t smb = smem_u32(sm);
  const uint32_t a_aA = smb + O_AA, a_B = smb + O_B;
  const uint32_t a_q = smb + O_Q, a_k = smb + O_K, a_v = smb + O_V;

  for (int i = tid; i < 8192; i += NTHREADS) {
    int r = i >> 6, c = i & 63;
    xs[r * 68 + c] =
        tok_emb[idx[b * 128 + r] * 64 + c] + pos_emb[(r & 63) * 64 + c];
  }
  __syncthreads();

  float acc[8][4];

  for (int l = 0; l < 4; l++) {
    if (tid < 128) {
      float v[64];
      ln_row(xs + tid * 68, v, ln1_g + l * 64, ln1_b + l * 64);
      row_to_A(v, aAc, tid);
    }
    // ---- Q,K,V GEMMs -> swizzled q/k/v tiles ----
    for (int m = 0; m < 3; m++) {
      stageB(g_wqkv + (l * 3 + m) * 4096, Bsc, tid);
      __syncthreads();
      gemm_core(a_aA, a_B, w, lane, acc);
      char* dst = sm + (m == 0 ? O_Q : m == 1 ? O_K : O_V);
#pragma unroll
      for (int nt = 0; nt < 8; nt++) {
        int col = nt * 8 + tg * 2;
        *(uint32_t*)(dst + SW(r0, col * 2)) = f2h2(acc[nt][0], acc[nt][1]);
        *(uint32_t*)(dst + SW(r0 + 8, col * 2)) = f2h2(acc[nt][2], acc[nt][3]);
      }
      __syncthreads();
    }
    // ---- attention on tensor cores; wo staged into idle B meanwhile ----
    stageB(g_wo + l * 4096, Bsc, tid);
    {
      const int bl = lane & 7;
      const int l15 = lane & 15;
      const int ahi = (lane >> 4) << 4;
      const int bhi = (lane & 8) << 1;
      const int seq0 = (w >> 2) * 64;
      const int tlo = (w & 3) * 16 + g;
      const int rowA = w * 16 + l15;
      const uint32_t q_base = a_q + rowA * 128;
      const int aswz = (rowA & 7) << 4;
#pragma unroll
      for (int h = 0; h < 4; h++) {
        float S[8][4];
#pragma unroll
        for (int nt = 0; nt < 8; nt++)
#pragma unroll
          for (int e = 0; e < 4; e++) S[nt][e] = 0.f;
        uint32_t a0, a1, a2, a3;
        LDSM_X4(a0, a1, a2, a3, q_base + ((h * 32 + ahi) ^ aswz));
#pragma unroll
        for (int nt = 0; nt < 8; nt++) {
          uint32_t b0, b1;
          LDSM_X2(b0, b1, a_k + SW(seq0 + nt * 8 + bl, h * 32 + bhi));
          MMA16816(S[nt], a0, a1, a2, a3, b0, b1);
        }
        float mx0 = -1e30f, mx1 = -1e30f;
#pragma unroll
        for (int nt = 0; nt < 8; nt++) {
          int c0 = nt * 8 + tg * 2;
          S[nt][0] = (c0 <= tlo) ? S[nt][0] * 0.25f : -1e30f;
          S[nt][1] = (c0 + 1 <= tlo) ? S[nt][1] * 0.25f : -1e30f;
          S[nt][2] = (c0 <= tlo + 8) ? S[nt][2] * 0.25f : -1e30f;
          S[nt][3] = (c0 + 1 <= tlo + 8) ? S[nt][3] * 0.25f : -1e30f;
          mx0 = fmaxf(mx0, fmaxf(S[nt][0], S[nt][1]));
          mx1 = fmaxf(mx1, fmaxf(S[nt][2], S[nt][3]));
        }
        mx0 = fmaxf(mx0, __shfl_xor_sync(0xffffffffu, mx0, 1));
        mx0 = fmaxf(mx0, __shfl_xor_sync(0xffffffffu, mx0, 2));
        mx1 = fmaxf(mx1, __shfl_xor_sync(0xffffffffu, mx1, 1));
        mx1 = fmaxf(mx1, __shfl_xor_sync(0xffffffffu, mx1, 2));
        float sum0 = 0.f, sum1 = 0.f;
#pragma unroll
        for (int nt = 0; nt < 8; nt++) {
          S[nt][0] = __expf(S[nt][0] - mx0);
          S[nt][1] = __expf(S[nt][1] - mx0);
          S[nt][2] = __expf(S[nt][2] - mx1);
          S[nt][3] = __expf(S[nt][3] - mx1);
          sum0 += S[nt][0] + S[nt][1];
          sum1 += S[nt][2] + S[nt][3];
        }
        sum0 += __shfl_xor_sync(0xffffffffu, sum0, 1);
        sum0 += __shfl_xor_sync(0xffffffffu, sum0, 2);
        sum1 += __shfl_xor_sync(0xffffffffu, sum1, 1);
        sum1 += __shfl_xor_sync(0xffffffffu, sum1, 2);
        float ri0 = 1.f / sum0, ri1 = 1.f / sum1;
        uint32_t Pa[4][4];
#pragma unroll
        for (int kb = 0; kb < 4; kb++) {
          Pa[kb][0] = f2h2(S[2 * kb][0] * ri0, S[2 * kb][1] * ri0);
          Pa[kb][1] = f2h2(S[2 * kb][2] * ri1, S[2 * kb][3] * ri1);
          Pa[kb][2] = f2h2(S[2 * kb + 1][0] * ri0, S[2 * kb + 1][1] * ri0);
          Pa[kb][3] = f2h2(S[2 * kb + 1][2] * ri1, S[2 * kb + 1][3] * ri1);
        }
        float O[2][4];
#pragma unroll
        for (int nt = 0; nt < 2; nt++)
#pragma unroll
          for (int e = 0; e < 4; e++) O[nt][e] = 0.f;
#pragma unroll
        for (int kb = 0; kb < 4; kb++) {
          int ur = seq0 + kb * 16 + bl + ((lane & 8) ? 8 : 0);
#pragma unroll
          for (int nt = 0; nt < 2; nt++) {
            uint32_t b0, b1;
            LDSM_X2T(b0, b1, a_v + SW(ur, h * 32 + nt * 16));
            MMA16816(O[nt], Pa[kb][0], Pa[kb][1], Pa[kb][2], Pa[kb][3], b0, b1);
          }
        }
#pragma unroll
        for (int nt = 0; nt < 2; nt++) {
          int col = h * 16 + nt * 8 + tg * 2;
          *(uint32_t*)(aAc + SW(r0, col * 2)) = f2h2(O[nt][0], O[nt][1]);
          *(uint32_t*)(aAc + SW(r0 + 8, col * 2)) = f2h2(O[nt][2], O[nt][3]);
        }
      }
    }
    __syncthreads();
    // ---- WO GEMM (wo already staged): xs += d + bo ----
    gemm_core(a_aA, a_B, w, lane, acc);
    {
      const float* bp = bo + l * 64;
#pragma unroll
      for (int nt = 0; nt < 8; nt++) {
        int col = nt * 8 + tg * 2;
        float bv0 = __ldg(bp + col), bv1 = __ldg(bp + col + 1);
        xs[r0 * 68 + col] += acc[nt][0] + bv0;
        xs[r0 * 68 + col + 1] += acc[nt][1] + bv1;
        xs[(r0 + 8) * 68 + col] += acc[nt][2] + bv0;
        xs[(r0 + 8) * 68 + col + 1] += acc[nt][3] + bv1;
      }
    }
    __syncthreads();
    if (tid < 128) {
      float v[64];
      ln_row(xs + tid * 68, v, ln2_g + l * 64, ln2_b + l * 64);
      row_to_A(v, aAc, tid);
    }
    // ---- MLP: w1 chunk in O_B, w2 chunk staged into dead O_K ----
    char* aMc = sm + O_Q;
    const uint32_t a_aM = a_q;
    for (int j = 0; j < 4; j++) {
      stageB(g_w1 + (l * 4 + j) * 4096, Bsc, tid);
      stageB(g_w2 + (l * 4 + j) * 4096, sm + O_K, tid);
      __syncthreads();
      gemm_core(a_aA, a_B, w, lane, acc);
      {
        const float* bp = b1 + l * 256 + j * 64;
#pragma unroll
        for (int nt = 0; nt < 8; nt++) {
          int col = nt * 8 + tg * 2;
          float bv0 = __ldg(bp + col), bv1 = __ldg(bp + col + 1);
          *(uint32_t*)(aMc + SW(r0, col * 2)) = f2h2(
              fmaxf(acc[nt][0] + bv0, 0.f), fmaxf(acc[nt][1] + bv1, 0.f));
          *(uint32_t*)(aMc + SW(r0 + 8, col * 2)) = f2h2(
              fmaxf(acc[nt][2] + bv0, 0.f), fmaxf(acc[nt][3] + bv1, 0.f));
        }
      }
      __syncthreads();
      gemm_core(a_aM, a_k, w, lane, acc);
      {
        const float* bp = (j == 3) ? (b2 + l * 64) : nullptr;
#pragma unroll
        for (int nt = 0; nt < 8; nt++) {
          int col = nt * 8 + tg * 2;
          float bv0 = bp ? __ldg(bp + col) : 0.f;
          float bv1 = bp ? __ldg(bp + col + 1) : 0.f;
          xs[r0 * 68 + col] += acc[nt][0] + bv0;
          xs[r0 * 68 + col + 1] += acc[nt][1] + bv1;
          xs[(r0 + 8) * 68 + col] += acc[nt][2] + bv0;
          xs[(r0 + 8) * 68 + col + 1] += acc[nt][3] + bv1;
        }
      }
      __syncthreads();
    }
  }

  // ---- final LN -> split fp16 operands Ah @ O_AA, Al @ O_Q ----
  if (tid < 128) {
    float v[64];
    ln_row(xs + tid * 68, v, lnf_g, lnf_b);
    char* Alc = sm + O_Q;
#pragma unroll
    for (int q8 = 0; q8 < 8; q8++) {
      uint32_t hh[4], hl[4];
#pragma unroll
      for (int e = 0; e < 4; e++) {
        float v0 = v[q8 * 8 + e * 2], v1 = v[q8 * 8 + e * 2 + 1];
        __half h0 = __float2half(v0), h1 = __float2half(v1);
        hh[e] = f2h2(v0, v1);  // rn: close enough to h0/h1 pair
        __half2 hi2 = *(__half2*)&hh[e];
        float2 hif = __half22float2(hi2);
        hl[e] = f2h2(v0 - hif.x, v1 - hif.y);
        (void)h0; (void)h1;
      }
      *(uint4*)(aAc + SW(tid, q8 * 16)) = *(uint4*)hh;
      *(uint4*)(Alc + SW(tid, q8 * 16)) = *(uint4*)hl;
    }
  }
  // stage lm_w hi/lo [96][64] into O_K region
  stageB96(g_lmh, sm + O_K, tid);
  stageB96(g_lml, sm + O_K + 12288, tid);
  __syncthreads();

  // ---- LM head: 128x96x64 split GEMM on tensor cores ----
  float lacc[12][4];
#pragma unroll
  for (int nt = 0; nt < 12; nt++)
#pragma unroll
    for (int e = 0; e < 4; e++) lacc[nt][e] = 0.f;
  lm_pass(a_aA, a_k, w, lane, lacc);          // Ah @ Bh
  lm_pass(a_q, a_k, w, lane, lacc);           // Al @ Bh
  lm_pass(a_aA, a_k + 12288, w, lane, lacc);  // Ah @ Bl
  __syncthreads();  // all reads of Al/Bh/Bl done; O_Q region now logits

  float* sl = (float*)(sm + O_Q);
  {
#pragma unroll
    for (int nt = 0; nt < 12; nt++) {
      int col = nt * 8 + tg * 2;
      float bv0 = __ldg(lm_b + col), bv1 = __ldg(lm_b + col + 1);
      float o00 = lacc[nt][0] + bv0, o01 = lacc[nt][1] + bv1;
      float o10 = lacc[nt][2] + bv0, o11 = lacc[nt][3] + bv1;
      sl[r0 * 96 + col] = o00;
      sl[r0 * 96 + col + 1] = o01;
      sl[(r0 + 8) * 96 + col] = o10;
      sl[(r0 + 8) * 96 + col + 1] = o11;
      if (write_logits) {
        float* ob = out + (size_t)(b * 128 + r0) * 96 + col;
        ob[0] = o00; ob[1] = o01;
        ob[8 * 96] = o10; ob[8 * 96 + 1] = o11;
      }
    }
  }
  __syncthreads();

  // ---- loss ----
  {
    int r = tid >> 1, p = tid & 1;
    const float* row = sl + r * 96 + p * 48;
    float m = -1e30f;
#pragma unroll
    for (int j = 0; j < 48; j++) m = fmaxf(m, row[j]);
    m = fmaxf(m, __shfl_xor_sync(0xffffffffu, m, 1));
    float se = 0.f;
#pragma unroll
    for (int j = 0; j < 48; j++) se += __expf(row[j] - m);
    se += __shfl_xor_sync(0xffffffffu, se, 1);
    float lse = m + logf(se);
    int tgt = targets[b * 128 + r];
    float contrib = 0.f;
    int rel = tgt - p * 48;
    if (rel >= 0 && rel < 48) contrib = row[rel] - lse;
    contrib += __shfl_xor_sync(0xffffffffu, contrib, 1);
    if (p == 0) sred[r] = contrib;
  }
  __syncthreads();
  if (tid < 128) {
    float v = sred[tid];
#pragma unroll
    for (int o = 16; o; o >>= 1) v += __shfl_xor_sync(0xffffffffu, v, o);
    if ((tid & 31) == 0) sred[128 + (tid >> 5)] = v;
  }
  __syncthreads();
  if (tid == 0)
    g_partial[b] = sred[128] + sred[129] + sred[130] + sred[131];
}

__global__ void loss_reduce_kernel(float* __restrict__ dst) {
  __shared__ float sh[8];
  float v = 0.f;
  for (int i = threadIdx.x; i < NCTAS; i += NTHREADS) v += g_partial[i];
#pragma unroll
  for (int o = 16; o; o >>= 1) v += __shfl_xor_sync(0xffffffffu, v, o);
  if ((threadIdx.x & 31) == 0) sh[threadIdx.x >> 5] = v;
  __syncthreads();
  if (threadIdx.x == 0) {
    float s = 0.f;
    for (int w = 0; w < 8; w++) s += sh[w];
    dst[0] = -s / (float)(4096 * 64);
  }
}

extern "C" void kernel_launch(void* const* d_in, const int* in_sizes, int n_in,
                              void* d_out, int out_size) {
  const int* idx = (const int*)d_in[0];
  const int* targets = (const int*)d_in[1];
  const float* tok_emb = (const float*)d_in[2];
  const float* pos_emb = (const float*)d_in[3];
  const float* ln1_g = (const float*)d_in[4];
  const float* ln1_b = (const float*)d_in[5];
  const float* wq = (const float*)d_in[6];
  const float* wk = (const float*)d_in[7];
  const float* wv = (const float*)d_in[8];
  const float* wo = (const float*)d_in[9];
  const float* bo = (const float*)d_in[10];
  const float* ln2_g = (const float*)d_in[11];
  const float* ln2_b = (const float*)d_in[12];
  const float* w1 = (const float*)d_in[13];
  const float* b1 = (const float*)d_in[14];
  const float* w2 = (const float*)d_in[15];
  const float* b2 = (const float*)d_in[16];
  const float* lnf_g = (const float*)d_in[17];
  const float* lnf_b = (const float*)d_in[18];
  const float* lm_w = (const float*)d_in[19];
  const float* lm_b = (const float*)d_in[20];
  float* out = (float*)d_out;

  cudaFuncSetAttribute(slm_kernel, cudaFuncAttributeMaxDynamicSharedMemorySize,
                       SMEM_BYTES);

  prep_kernel<<<792, 256>>>(wq, wk, wv, wo, w1, w2, lm_w);

  int write_logits = (out_size >= BTV) ? 1 : 0;
  slm_kernel<<<NCTAS, NTHREADS, SMEM_BYTES>>>(
      idx, targets, tok_emb, pos_emb, ln1_g, ln1_b, bo, ln2_g, ln2_b, b1, b2,
      lnf_g, lnf_b, lm_b, out, write_logits);

  if (out_size > BTV)
    loss_reduce_kernel<<<1, NTHREADS>>>(out + BTV);
  else if (out_size < BTV)
    loss_reduce_kernel<<<1, NTHREADS>>>(out);
}